// round 9
// baseline (speedup 1.0000x reference)
#include <cuda_runtime.h>
#include <cuda_fp16.h>
#include <cstdint>
#include <cstddef>

#define N_B   2
#define S_LEN 2048
#define HEADS 16
#define HDIM  64
#define EMB   1024
// 1/sqrt(1024) * log2(e): softmax runs in exp2 domain
#define QSCALE (0.03125f * 1.44269504088896340736f)
#define FULLM 0xffffffffu

// Scratch (alloc-free rule: __device__ globals), fp16.
__device__ __half g_qp[N_B * S_LEN * EMB];
__device__ __half g_kp[N_B * S_LEN * EMB];
__device__ __half g_vp[N_B * S_LEN * EMB];   // (n,s,h,d) projected V
__device__ __half g_vt[N_B * HEADS * HDIM * S_LEN]; // (n,h,d,s) transposed V
__device__ __half g_ao[N_B * S_LEN * EMB];
__device__ __half g_wo[EMB * EMB];

__device__ __forceinline__ uint32_t packh2(float lo, float hi) {
    __half2 h = __floats2half2_rn(lo, hi);
    return *(uint32_t*)&h;
}
// exp2 on a packed half2 (one MUFU op for two values)
__device__ __forceinline__ uint32_t h2ex2(uint32_t x) {
    uint32_t r;
    asm("ex2.approx.f16x2 %0, %1;" : "=r"(r) : "r"(x));
    return r;
}
#define LDU32(p) (*(const uint32_t*)(p))

// D(16x8) += A(16x16)*B(16x8), fp16 in, fp32 accum.
__device__ __forceinline__ void mma16(float* c, const uint32_t* a,
                                      uint32_t b0, uint32_t b1) {
    asm volatile(
        "mma.sync.aligned.m16n8k16.row.col.f32.f16.f16.f32 "
        "{%0,%1,%2,%3},{%4,%5,%6,%7},{%8,%9},{%0,%1,%2,%3};"
        : "+f"(c[0]), "+f"(c[1]), "+f"(c[2]), "+f"(c[3])
        : "r"(a[0]), "r"(a[1]), "r"(a[2]), "r"(a[3]), "r"(b0), "r"(b1));
}

__device__ __forceinline__ void cpa16(uint32_t s, const void* g) {
    asm volatile("cp.async.ca.shared.global [%0], [%1], 16;" :: "r"(s), "l"(g));
}
__device__ __forceinline__ void cpa_commit() {
    asm volatile("cp.async.commit_group;");
}

// ---------------------------------------------------------------------------
// Wo fp32 -> fp16
// ---------------------------------------------------------------------------
__global__ __launch_bounds__(256) void cvt_wo(const float* __restrict__ W,
                                              __half* __restrict__ Y) {
    int i = (blockIdx.x * 256 + threadIdx.x) * 4;
    float4 v = *(const float4*)(W + i);
    uint2 o = make_uint2(packh2(v.x, v.y), packh2(v.z, v.w));
    *(uint2*)(Y + i) = o;
}

// ---------------------------------------------------------------------------
// Projection: Y(65536x64) fp16 = rn_h((X @ W^T) * sc).  Q gets QSCALE.
// ---------------------------------------------------------------------------
#define PSTR 72
__global__ __launch_bounds__(128) void proj_tc(const float* __restrict__ xq,
                                               const float* __restrict__ xk,
                                               const float* __restrict__ xv,
                                               const float* __restrict__ wq,
                                               const float* __restrict__ wk,
                                               const float* __restrict__ wv,
                                               __half* __restrict__ yq,
                                               __half* __restrict__ yk,
                                               __half* __restrict__ yv) {
    __shared__ __half Xs[64 * PSTR];
    __shared__ __half Ws[64 * PSTR];
    const int t = threadIdx.x, lane = t & 31, warp = t >> 5;
    const int tq = lane & 3, gq = lane >> 2;
    const int wm = warp * 16;
    const int rowBase = blockIdx.x * 64;
    const int which = blockIdx.y;
    const float* X = (which == 0) ? xq : (which == 1) ? xk : xv;
    const float* W = (which == 0) ? wq : (which == 1) ? wk : wv;
    __half* Y = (which == 0) ? yq : (which == 1) ? yk : yv;
    const float sc = (which == 0) ? QSCALE : 1.0f;

#pragma unroll
    for (int i = 0; i < 8; i++) {
        int idx = i * 128 + t;
        int r = idx >> 4, c = (idx & 15) << 2;
        float4 v = *(const float4*)(X + (size_t)(rowBase + r) * 64 + c);
        *(uint2*)(&Xs[r * PSTR + c]) = make_uint2(packh2(v.x, v.y), packh2(v.z, v.w));
        float4 w = *(const float4*)(W + r * 64 + c);
        *(uint2*)(&Ws[r * PSTR + c]) = make_uint2(packh2(w.x, w.y), packh2(w.z, w.w));
    }
    __syncthreads();

    float c[8][4] = {};
#pragma unroll
    for (int kg = 0; kg < 4; kg++) {
        const int kk = kg * 16 + 2 * tq;
        uint32_t a[4] = { LDU32(&Xs[(wm + gq) * PSTR + kk]),
                          LDU32(&Xs[(wm + gq + 8) * PSTR + kk]),
                          LDU32(&Xs[(wm + gq) * PSTR + kk + 8]),
                          LDU32(&Xs[(wm + gq + 8) * PSTR + kk + 8]) };
        uint32_t b0[8], b1[8];
#pragma unroll
        for (int nb = 0; nb < 8; nb++) {
            b0[nb] = LDU32(&Ws[(nb * 8 + gq) * PSTR + kk]);
            b1[nb] = LDU32(&Ws[(nb * 8 + gq) * PSTR + kk + 8]);
        }
#pragma unroll
        for (int nb = 0; nb < 8; nb++) mma16(c[nb], a, b0[nb], b1[nb]);
    }
#pragma unroll
    for (int nb = 0; nb < 8; nb++) {
        size_t base = (size_t)(rowBase + wm + gq) * 64 + nb * 8 + 2 * tq;
        *(uint32_t*)(Y + base) = packh2(c[nb][0] * sc, c[nb][1] * sc);
        *(uint32_t*)(Y + base + 8 * 64) = packh2(c[nb][2] * sc, c[nb][3] * sc);
    }
}

// ---------------------------------------------------------------------------
// V transpose: vp (n,s,h,d) -> vt (n,h,d,s).
// ---------------------------------------------------------------------------
__global__ __launch_bounds__(256) void transp_v(const __half* __restrict__ vp,
                                                __half* __restrict__ vt) {
    __shared__ __half Ts[64][66];
    const int t = threadIdx.x;
    const int s0 = blockIdx.x * 64;
    const int nh = blockIdx.y;
    const int n = nh >> 4, h = nh & 15;
    const __half* src = vp + ((size_t)n * S_LEN * HEADS + h) * HDIM;
#pragma unroll
    for (int i = 0; i < 8; i++) {
        int id = i * 256 + t;
        int r = id >> 5;
        int c = (id & 31) * 2;
        __half2 v = *(const __half2*)(src + (size_t)(s0 + r) * EMB + c);
        Ts[c][r] = v.x;
        Ts[c + 1][r] = v.y;
    }
    __syncthreads();
    __half* dst = vt + (size_t)nh * HDIM * S_LEN;
#pragma unroll
    for (int i = 0; i < 8; i++) {
        int id = i * 256 + t;
        int d = id >> 5;
        int s = (id & 31) * 2;
        __half2 v;
        v.x = Ts[d][s];
        v.y = Ts[d][s + 1];
        *(__half2*)(dst + (size_t)d * S_LEN + s0 + s) = v;
    }
}

// ---------------------------------------------------------------------------
// Flash attention fp16, fixed-max exp2 softmax via ex2.approx.f16x2.
// 3-stage cp.async ring, ONE __syncthreads per tile (warps may drift a full
// tile, overlapping softmax of one warp with MMAs of others).
// grid=(S/128, N*H), 256 thr = 8 warps, BM=128, BN=64.
// ---------------------------------------------------------------------------
#define KSTRH 72
#define KELEH (64 * KSTRH)
#define STAGEH (2 * KELEH)      // K tile + V tile
#define NSTG 3
#define NT (S_LEN / 64)

extern __shared__ __half fa_smem[];

__global__ __launch_bounds__(256) void flash_tc(const __half* __restrict__ Q,
                                                const __half* __restrict__ K,
                                                const __half* __restrict__ Vt,
                                                __half* __restrict__ O) {
    __half* smem = fa_smem;
    const int t = threadIdx.x, lane = t & 31, warp = t >> 5;
    const int tq = lane & 3, gq = lane >> 2;
    const int wm = warp * 16;
    const int qt = blockIdx.x, nh = blockIdx.y;
    const int n = nh >> 4, h = nh & 15;
    const size_t headOff = ((size_t)n * S_LEN * HEADS + h) * HDIM;
    const __half* qb = Q + headOff;
    const __half* kb = K + headOff;
    const __half* vtb = Vt + (size_t)nh * HDIM * S_LEN;
    const int q0 = qt * 128;
    const uint32_t sb = (uint32_t)__cvta_generic_to_shared(smem);

    // stage Q tile (128x64 halves) into buffer 0, pull A-frags into regs
#pragma unroll
    for (int i = 0; i < 4; i++) {
        int id = i * 256 + t;
        int r = id >> 3, c = (id & 7) << 3;
        cpa16(sb + (r * KSTRH + c) * 2, qb + (size_t)(q0 + r) * EMB + c);
    }
    cpa_commit();
    asm volatile("cp.async.wait_group 0;");
    __syncthreads();
    uint32_t aQ[4][4];
#pragma unroll
    for (int kg = 0; kg < 4; kg++) {
        const int kk = kg * 16 + 2 * tq;
        aQ[kg][0] = LDU32(&smem[(wm + gq) * KSTRH + kk]);
        aQ[kg][1] = LDU32(&smem[(wm + gq + 8) * KSTRH + kk]);
        aQ[kg][2] = LDU32(&smem[(wm + gq) * KSTRH + kk + 8]);
        aQ[kg][3] = LDU32(&smem[(wm + gq + 8) * KSTRH + kk + 8]);
    }
    __syncthreads();

    // ring prologue: prefetch tiles 0 and 1 (one commit group each)
#pragma unroll
    for (int pre = 0; pre < 2; pre++) {
        const int k0 = pre * 64;
        const uint32_t dst = sb + pre * STAGEH * 2;
#pragma unroll
        for (int i = 0; i < 2; i++) {
            int id = i * 256 + t;
            int r = id >> 3, c = (id & 7) << 3;
            cpa16(dst + (r * KSTRH + c) * 2, kb + (size_t)(k0 + r) * EMB + c);
            cpa16(dst + (KELEH + r * KSTRH + c) * 2,
                  vtb + (size_t)r * S_LEN + k0 + c);
        }
        cpa_commit();
    }

    float o[8][4] = {};
    float l0 = 0.f, l1 = 0.f;
    int bufc = 0;   // compute buffer; prefetch target = (bufc+2)%3

    for (int kt = 0; kt < NT; kt++) {
        if (kt + 1 < NT) {
            asm volatile("cp.async.wait_group 1;");
        } else {
            asm volatile("cp.async.wait_group 0;");
        }
        // one barrier: tile-kt data visible block-wide AND all warps are done
        // reading buffer (kt-1)%3 == prefetch target (kt+2)%3.
        __syncthreads();

        if (kt + 2 < NT) {
            const int k0 = (kt + 2) * 64;
            int bufp = bufc + 2; if (bufp >= NSTG) bufp -= NSTG;
            const uint32_t dst = sb + bufp * STAGEH * 2;
#pragma unroll
            for (int i = 0; i < 2; i++) {
                int id = i * 256 + t;
                int r = id >> 3, c = (id & 7) << 3;
                cpa16(dst + (r * KSTRH + c) * 2, kb + (size_t)(k0 + r) * EMB + c);
                cpa16(dst + (KELEH + r * KSTRH + c) * 2,
                      vtb + (size_t)r * S_LEN + k0 + c);
            }
            cpa_commit();
        }

        const __half* Ksm = smem + bufc * STAGEH;
        const __half* Vsm = smem + bufc * STAGEH + KELEH;
        bufc = (bufc + 1 < NSTG) ? bufc + 1 : 0;

        // S = Q K^T (log2e-scale baked into Q)
        float c_[8][4] = {};
#pragma unroll
        for (int kg = 0; kg < 4; kg++) {
            const int kk = kg * 16 + 2 * tq;
            uint32_t b0[8], b1[8];
#pragma unroll
            for (int nb = 0; nb < 8; nb++) {
                b0[nb] = LDU32(&Ksm[(nb * 8 + gq) * KSTRH + kk]);
                b1[nb] = LDU32(&Ksm[(nb * 8 + gq) * KSTRH + kk + 8]);
            }
#pragma unroll
            for (int nb = 0; nb < 8; nb++) mma16(c_[nb], aQ[kg], b0[nb], b1[nb]);
        }

        // P = exp2(S): pack fp32 pairs -> half2, ONE MUFU per pair.
        // hp01/hp23 are directly the PV A-fragment words.
        uint32_t hp01[8], hp23[8];
#pragma unroll
        for (int nb = 0; nb < 8; nb++) {
            hp01[nb] = h2ex2(packh2(c_[nb][0], c_[nb][1]));
            hp23[nb] = h2ex2(packh2(c_[nb][2], c_[nb][3]));
            float2 f0 = __half22float2(*(__half2*)&hp01[nb]);
            float2 f1 = __half22float2(*(__half2*)&hp23[nb]);
            l0 += f0.x + f0.y;
            l1 += f1.x + f1.y;
        }

        // O += P V
#pragma unroll
        for (int g = 0; g < 4; g++) {
            uint32_t aP[4] = { hp01[2 * g], hp23[2 * g],
                               hp01[2 * g + 1], hp23[2 * g + 1] };
            const int kk = g * 16 + 2 * tq;
            uint32_t b0[8], b1[8];
#pragma unroll
            for (int nb = 0; nb < 8; nb++) {
                b0[nb] = LDU32(&Vsm[(nb * 8 + gq) * KSTRH + kk]);
                b1[nb] = LDU32(&Vsm[(nb * 8 + gq) * KSTRH + kk + 8]);
            }
#pragma unroll
            for (int nb = 0; nb < 8; nb++) mma16(o[nb], aP, b0[nb], b1[nb]);
        }
    }

    // one-shot denominator reduction across the quad
#pragma unroll
    for (int off = 1; off <= 2; off <<= 1) {
        l0 += __shfl_xor_sync(FULLM, l0, off);
        l1 += __shfl_xor_sync(FULLM, l1, off);
    }
    const float inv0 = 1.0f / l0, inv1 = 1.0f / l1;
#pragma unroll
    for (int nb = 0; nb < 8; nb++) {
        size_t base = headOff + (size_t)(q0 + wm + gq) * EMB + nb * 8 + 2 * tq;
        *(uint32_t*)(O + base) = packh2(o[nb][0] * inv0, o[nb][1] * inv0);
        *(uint32_t*)(O + base + (size_t)8 * EMB) =
            packh2(o[nb][2] * inv1, o[nb][3] * inv1);
    }
}

// ---------------------------------------------------------------------------
// Output GEMM: Y(4096x1024) fp32 = X @ Wo^T + bo.  BM=128, BN=128, BK=64.
// 3-stage ring, one barrier per k-tile.  grid = 256 (single wave), 8 warps.
// ---------------------------------------------------------------------------
#define OSTRH 72
#define XELEH (128 * OSTRH)
#define OSTAGEH (2 * XELEH)
#define NKT (EMB / 64)

extern __shared__ __half og_smem[];

__global__ __launch_bounds__(256) void out_tc(const __half* __restrict__ X,
                                              const __half* __restrict__ W,
                                              const float* __restrict__ bias,
                                              float* __restrict__ Y) {
    __half* smem = og_smem;
    const int t = threadIdx.x, lane = t & 31, warp = t >> 5;
    const int tq = lane & 3, gq = lane >> 2;
    const int wm = warp * 16;
    const int m0 = blockIdx.x * 128, n0 = blockIdx.y * 128;
    const uint32_t sb = (uint32_t)__cvta_generic_to_shared(smem);

#pragma unroll
    for (int pre = 0; pre < 2; pre++) {
        const int k0 = pre * 64;
        const uint32_t dst = sb + pre * OSTAGEH * 2;
#pragma unroll
        for (int i = 0; i < 4; i++) {
            int id = i * 256 + t;
            int r = id >> 3, c = (id & 7) << 3;
            cpa16(dst + (r * OSTRH + c) * 2, X + (size_t)(m0 + r) * EMB + k0 + c);
            cpa16(dst + (XELEH + r * OSTRH + c) * 2,
                  W + (size_t)(n0 + r) * EMB + k0 + c);
        }
        cpa_commit();
    }

    float acc[16][4] = {};
    int bufc = 0;
    for (int kt = 0; kt < NKT; kt++) {
        if (kt + 1 < NKT) {
            asm volatile("cp.async.wait_group 1;");
        } else {
            asm volatile("cp.async.wait_group 0;");
        }
        __syncthreads();

        if (kt + 2 < NKT) {
            const int k0 = (kt + 2) * 64;
            int bufp = bufc + 2; if (bufp >= NSTG) bufp -= NSTG;
            const uint32_t dst = sb + bufp * OSTAGEH * 2;
#pragma unroll
            for (int i = 0; i < 4; i++) {
                int id = i * 256 + t;
                int r = id >> 3, c = (id & 7) << 3;
                cpa16(dst + (r * OSTRH + c) * 2, X + (size_t)(m0 + r) * EMB + k0 + c);
                cpa16(dst + (XELEH + r * OSTRH + c) * 2,
                      W + (size_t)(n0 + r) * EMB + k0 + c);
            }
            cpa_commit();
        }

        const __half* Xsm = smem + bufc * OSTAGEH;
        const __half* Wsm = smem + bufc * OSTAGEH + XELEH;
        bufc = (bufc + 1 < NSTG) ? bufc + 1 : 0;
#pragma unroll
        for (int kg = 0; kg < 4; kg++) {
            const int kk = kg * 16 + 2 * tq;
            uint32_t a[4] = { LDU32(&Xsm[(wm + gq) * OSTRH + kk]),
                              LDU32(&Xsm[(wm + gq + 8) * OSTRH + kk]),
                              LDU32(&Xsm[(wm + gq) * OSTRH + kk + 8]),
                              LDU32(&Xsm[(wm + gq + 8) * OSTRH + kk + 8]) };
#pragma unroll
            for (int half8 = 0; half8 < 2; half8++) {
                uint32_t b0[8], b1[8];
#pragma unroll
                for (int j = 0; j < 8; j++) {
                    int row = (half8 * 8 + j) * 8 + gq;
                    b0[j] = LDU32(&Wsm[row * OSTRH + kk]);
                    b1[j] = LDU32(&Wsm[row * OSTRH + kk + 8]);
                }
#pragma unroll
                for (int j = 0; j < 8; j++)
                    mma16(acc[half8 * 8 + j], a, b0[j], b1[j]);
            }
        }
    }

#pragma unroll
    for (int nb = 0; nb < 16; nb++) {
        int col = n0 + nb * 8 + 2 * tq;
        float b0 = __ldg(bias + col), b1 = __ldg(bias + col + 1);
        size_t base = (size_t)(m0 + wm + gq) * EMB + col;
        *(float2*)(Y + base) = make_float2(acc[nb][0] + b0, acc[nb][1] + b1);
        *(float2*)(Y + base + (size_t)8 * EMB) =
            make_float2(acc[nb][2] + b0, acc[nb][3] + b1);
    }
}

// ---------------------------------------------------------------------------
extern "C" void kernel_launch(void* const* d_in, const int* in_sizes, int n_in,
                              void* d_out, int out_size) {
    const float* q  = (const float*)d_in[0];
    const float* k  = (const float*)d_in[1];
    const float* v  = (const float*)d_in[2];
    const float* Wq = (const float*)d_in[3];
    const float* Wk = (const float*)d_in[4];
    const float* Wv = (const float*)d_in[5];
    const float* Wo = (const float*)d_in[6];
    const float* bo = (const float*)d_in[7];
    float* out = (float*)d_out;

    __half *qp, *kp, *vp, *vt, *ao, *wo;
    cudaGetSymbolAddress((void**)&qp, g_qp);
    cudaGetSymbolAddress((void**)&kp, g_kp);
    cudaGetSymbolAddress((void**)&vp, g_vp);
    cudaGetSymbolAddress((void**)&vt, g_vt);
    cudaGetSymbolAddress((void**)&ao, g_ao);
    cudaGetSymbolAddress((void**)&wo, g_wo);

    static bool attr_done = false;
    if (!attr_done) {
        cudaFuncSetAttribute(flash_tc, cudaFuncAttributeMaxDynamicSharedMemorySize,
                             NSTG * STAGEH * 2);
        cudaFuncSetAttribute(out_tc, cudaFuncAttributeMaxDynamicSharedMemorySize,
                             NSTG * OSTAGEH * 2);
        attr_done = true;
    }

    cvt_wo<<<1024, 256>>>(Wo, wo);
    proj_tc<<<dim3(1024, 3), 128>>>(q, k, v, Wq, Wk, Wv, qp, kp, vp);
    transp_v<<<dim3(S_LEN / 64, N_B * HEADS), 256>>>(vp, vt);
    flash_tc<<<dim3(S_LEN / 128, N_B * HEADS), 256, NSTG * STAGEH * 2>>>(qp, kp, vt, ao);
    out_tc<<<dim3((N_B * S_LEN) / 128, EMB / 128), 256, NSTG * OSTAGEH * 2>>>(ao, wo, bo, out);
}

// round 11
// speedup vs baseline: 1.1030x; 1.1030x over previous
#include <cuda_runtime.h>
#include <cuda_fp16.h>
#include <cstdint>
#include <cstddef>

#define N_B   2
#define S_LEN 2048
#define HEADS 16
#define HDIM  64
#define EMB   1024
// 1/sqrt(1024) * log2(e): softmax runs in exp2 domain
#define QSCALE (0.03125f * 1.44269504088896340736f)
#define FULLM 0xffffffffu

// Scratch (alloc-free rule: __device__ globals), fp16.
__device__ __half g_qp[N_B * S_LEN * EMB];
__device__ __half g_kp[N_B * S_LEN * EMB];
__device__ __half g_vp[N_B * S_LEN * EMB];   // (n,s,h,d) projected V
__device__ __half g_vt[N_B * HEADS * HDIM * S_LEN]; // (n,h,d,s) transposed V
__device__ __half g_ao[N_B * S_LEN * EMB];
__device__ __half g_wo[EMB * EMB];

__device__ __forceinline__ uint32_t packh2(float lo, float hi) {
    __half2 h = __floats2half2_rn(lo, hi);
    return *(uint32_t*)&h;
}
// exp2 on a packed half2 (one MUFU op for two values)
__device__ __forceinline__ uint32_t h2ex2(uint32_t x) {
    uint32_t r;
    asm("ex2.approx.f16x2 %0, %1;" : "=r"(r) : "r"(x));
    return r;
}
#define LDU32(p) (*(const uint32_t*)(p))

// D(16x8) += A(16x16)*B(16x8), fp16 in, fp32 accum.
__device__ __forceinline__ void mma16(float* c, const uint32_t* a,
                                      uint32_t b0, uint32_t b1) {
    asm volatile(
        "mma.sync.aligned.m16n8k16.row.col.f32.f16.f16.f32 "
        "{%0,%1,%2,%3},{%4,%5,%6,%7},{%8,%9},{%0,%1,%2,%3};"
        : "+f"(c[0]), "+f"(c[1]), "+f"(c[2]), "+f"(c[3])
        : "r"(a[0]), "r"(a[1]), "r"(a[2]), "r"(a[3]), "r"(b0), "r"(b1));
}

// 4x 8x8 b16 fragments in one shot, mma-ready layout
__device__ __forceinline__ void ldsm4(uint32_t& r0, uint32_t& r1,
                                      uint32_t& r2, uint32_t& r3, uint32_t a) {
    asm volatile("ldmatrix.sync.aligned.m8n8.x4.shared.b16 {%0,%1,%2,%3}, [%4];"
                 : "=r"(r0), "=r"(r1), "=r"(r2), "=r"(r3) : "r"(a));
}

__device__ __forceinline__ void cpa16(uint32_t s, const void* g) {
    asm volatile("cp.async.ca.shared.global [%0], [%1], 16;" :: "r"(s), "l"(g));
}
__device__ __forceinline__ void cpa_commit() {
    asm volatile("cp.async.commit_group;");
}

// ---------------------------------------------------------------------------
// Wo fp32 -> fp16
// ---------------------------------------------------------------------------
__global__ __launch_bounds__(256) void cvt_wo(const float* __restrict__ W,
                                              __half* __restrict__ Y) {
    int i = (blockIdx.x * 256 + threadIdx.x) * 4;
    float4 v = *(const float4*)(W + i);
    uint2 o = make_uint2(packh2(v.x, v.y), packh2(v.z, v.w));
    *(uint2*)(Y + i) = o;
}

// ---------------------------------------------------------------------------
// Projection: Y(65536x64) fp16 = rn_h((X @ W^T) * sc).  Q gets QSCALE.
// ---------------------------------------------------------------------------
#define PSTR 72
__global__ __launch_bounds__(128) void proj_tc(const float* __restrict__ xq,
                                               const float* __restrict__ xk,
                                               const float* __restrict__ xv,
                                               const float* __restrict__ wq,
                                               const float* __restrict__ wk,
                                               const float* __restrict__ wv,
                                               __half* __restrict__ yq,
                                               __half* __restrict__ yk,
                                               __half* __restrict__ yv) {
    __shared__ __half Xs[64 * PSTR];
    __shared__ __half Ws[64 * PSTR];
    const int t = threadIdx.x, lane = t & 31, warp = t >> 5;
    const int tq = lane & 3, gq = lane >> 2;
    const int wm = warp * 16;
    const int rowBase = blockIdx.x * 64;
    const int which = blockIdx.y;
    const float* X = (which == 0) ? xq : (which == 1) ? xk : xv;
    const float* W = (which == 0) ? wq : (which == 1) ? wk : wv;
    __half* Y = (which == 0) ? yq : (which == 1) ? yk : yv;
    const float sc = (which == 0) ? QSCALE : 1.0f;

#pragma unroll
    for (int i = 0; i < 8; i++) {
        int idx = i * 128 + t;
        int r = idx >> 4, c = (idx & 15) << 2;
        float4 v = *(const float4*)(X + (size_t)(rowBase + r) * 64 + c);
        *(uint2*)(&Xs[r * PSTR + c]) = make_uint2(packh2(v.x, v.y), packh2(v.z, v.w));
        float4 w = *(const float4*)(W + r * 64 + c);
        *(uint2*)(&Ws[r * PSTR + c]) = make_uint2(packh2(w.x, w.y), packh2(w.z, w.w));
    }
    __syncthreads();

    float c[8][4] = {};
#pragma unroll
    for (int kg = 0; kg < 4; kg++) {
        const int kk = kg * 16 + 2 * tq;
        uint32_t a[4] = { LDU32(&Xs[(wm + gq) * PSTR + kk]),
                          LDU32(&Xs[(wm + gq + 8) * PSTR + kk]),
                          LDU32(&Xs[(wm + gq) * PSTR + kk + 8]),
                          LDU32(&Xs[(wm + gq + 8) * PSTR + kk + 8]) };
        uint32_t b0[8], b1[8];
#pragma unroll
        for (int nb = 0; nb < 8; nb++) {
            b0[nb] = LDU32(&Ws[(nb * 8 + gq) * PSTR + kk]);
            b1[nb] = LDU32(&Ws[(nb * 8 + gq) * PSTR + kk + 8]);
        }
#pragma unroll
        for (int nb = 0; nb < 8; nb++) mma16(c[nb], a, b0[nb], b1[nb]);
    }
#pragma unroll
    for (int nb = 0; nb < 8; nb++) {
        size_t base = (size_t)(rowBase + wm + gq) * 64 + nb * 8 + 2 * tq;
        *(uint32_t*)(Y + base) = packh2(c[nb][0] * sc, c[nb][1] * sc);
        *(uint32_t*)(Y + base + 8 * 64) = packh2(c[nb][2] * sc, c[nb][3] * sc);
    }
}

// ---------------------------------------------------------------------------
// V transpose: vp (n,s,h,d) -> vt (n,h,d,s).
// ---------------------------------------------------------------------------
__global__ __launch_bounds__(256) void transp_v(const __half* __restrict__ vp,
                                                __half* __restrict__ vt) {
    __shared__ __half Ts[64][66];
    const int t = threadIdx.x;
    const int s0 = blockIdx.x * 64;
    const int nh = blockIdx.y;
    const int n = nh >> 4, h = nh & 15;
    const __half* src = vp + ((size_t)n * S_LEN * HEADS + h) * HDIM;
#pragma unroll
    for (int i = 0; i < 8; i++) {
        int id = i * 256 + t;
        int r = id >> 5;
        int c = (id & 31) * 2;
        __half2 v = *(const __half2*)(src + (size_t)(s0 + r) * EMB + c);
        Ts[c][r] = v.x;
        Ts[c + 1][r] = v.y;
    }
    __syncthreads();
    __half* dst = vt + (size_t)nh * HDIM * S_LEN;
#pragma unroll
    for (int i = 0; i < 8; i++) {
        int id = i * 256 + t;
        int d = id >> 5;
        int s = (id & 31) * 2;
        __half2 v;
        v.x = Ts[d][s];
        v.y = Ts[d][s + 1];
        *(__half2*)(dst + (size_t)d * S_LEN + s0 + s) = v;
    }
}

// ---------------------------------------------------------------------------
// Flash attention fp16: fixed-max exp2 softmax (f16x2 MUFU), 3-stage ring
// with one barrier per tile, ldmatrix.x4 fragment loads.
// grid=(S/128, N*H), 256 thr = 8 warps, BM=128, BN=64.
// ---------------------------------------------------------------------------
#define KSTRH 72
#define KELEH (64 * KSTRH)
#define STAGEH (2 * KELEH)      // K tile + V tile
#define NSTG 3
#define NT (S_LEN / 64)

extern __shared__ __half fa_smem[];

__global__ __launch_bounds__(256) void flash_tc(const __half* __restrict__ Q,
                                                const __half* __restrict__ K,
                                                const __half* __restrict__ Vt,
                                                __half* __restrict__ O) {
    __half* smem = fa_smem;
    const int t = threadIdx.x, lane = t & 31, warp = t >> 5;
    const int tq = lane & 3, gq = lane >> 2;
    const int wm = warp * 16;
    const int lrow = lane & 7, lmat = lane >> 3;
    const int qt = blockIdx.x, nh = blockIdx.y;
    const int n = nh >> 4, h = nh & 15;
    const size_t headOff = ((size_t)n * S_LEN * HEADS + h) * HDIM;
    const __half* qb = Q + headOff;
    const __half* kb = K + headOff;
    const __half* vtb = Vt + (size_t)nh * HDIM * S_LEN;
    const int q0 = qt * 128;
    const uint32_t sb = (uint32_t)__cvta_generic_to_shared(smem);
    // per-lane invariant offset for B-fragment ldmatrix (bytes)
    const uint32_t lanoffB =
        (uint32_t)((((lmat >> 1) * 8 + lrow) * KSTRH + (lmat & 1) * 8) * 2);

    // stage Q tile (128x64 halves) into buffer 0, pull A-frags into regs
#pragma unroll
    for (int i = 0; i < 4; i++) {
        int id = i * 256 + t;
        int r = id >> 3, c = (id & 7) << 3;
        cpa16(sb + (r * KSTRH + c) * 2, qb + (size_t)(q0 + r) * EMB + c);
    }
    cpa_commit();
    asm volatile("cp.async.wait_group 0;");
    __syncthreads();
    uint32_t aQ[4][4];
    {
        // A-frag ldmatrix: matrices (rows wm+0..7,col kk) (wm+8..15,kk)
        // (wm+0..7,kk+8) (wm+8..15,kk+8)
        const uint32_t lanoffA =
            (uint32_t)((((lmat & 1) * 8 + lrow) * KSTRH + (lmat >> 1) * 8) * 2);
#pragma unroll
        for (int kg = 0; kg < 4; kg++)
            ldsm4(aQ[kg][0], aQ[kg][1], aQ[kg][2], aQ[kg][3],
                  sb + (uint32_t)(wm * KSTRH * 2) + lanoffA + kg * 32);
    }
    __syncthreads();

    // ring prologue: prefetch tiles 0 and 1
#pragma unroll
    for (int pre = 0; pre < 2; pre++) {
        const int k0 = pre * 64;
        const uint32_t dst = sb + pre * STAGEH * 2;
#pragma unroll
        for (int i = 0; i < 2; i++) {
            int id = i * 256 + t;
            int r = id >> 3, c = (id & 7) << 3;
            cpa16(dst + (r * KSTRH + c) * 2, kb + (size_t)(k0 + r) * EMB + c);
            cpa16(dst + (KELEH + r * KSTRH + c) * 2,
                  vtb + (size_t)r * S_LEN + k0 + c);
        }
        cpa_commit();
    }

    float o[8][4] = {};
    float l0 = 0.f, l1 = 0.f;
    int bufc = 0;   // compute buffer; prefetch target = (bufc+2)%3

    for (int kt = 0; kt < NT; kt++) {
        if (kt + 1 < NT) {
            asm volatile("cp.async.wait_group 1;");
        } else {
            asm volatile("cp.async.wait_group 0;");
        }
        __syncthreads();

        if (kt + 2 < NT) {
            const int k0 = (kt + 2) * 64;
            int bufp = bufc + 2; if (bufp >= NSTG) bufp -= NSTG;
            const uint32_t dst = sb + bufp * STAGEH * 2;
#pragma unroll
            for (int i = 0; i < 2; i++) {
                int id = i * 256 + t;
                int r = id >> 3, c = (id & 7) << 3;
                cpa16(dst + (r * KSTRH + c) * 2, kb + (size_t)(k0 + r) * EMB + c);
                cpa16(dst + (KELEH + r * KSTRH + c) * 2,
                      vtb + (size_t)r * S_LEN + k0 + c);
            }
            cpa_commit();
        }

        const uint32_t kbase = sb + bufc * (STAGEH * 2) + lanoffB;
        const uint32_t vbase = kbase + KELEH * 2;
        bufc = (bufc + 1 < NSTG) ? bufc + 1 : 0;

        // S = Q K^T (log2e-scale baked into Q); B-frags via ldmatrix.x4
        float c_[8][4] = {};
#pragma unroll
        for (int kg = 0; kg < 4; kg++) {
            uint32_t bf[4][4];
#pragma unroll
            for (int p = 0; p < 4; p++)
                ldsm4(bf[p][0], bf[p][1], bf[p][2], bf[p][3],
                      kbase + (p * 16 * KSTRH + kg * 16) * 2);
#pragma unroll
            for (int p = 0; p < 4; p++) {
                mma16(c_[2 * p], aQ[kg], bf[p][0], bf[p][1]);
                mma16(c_[2 * p + 1], aQ[kg], bf[p][2], bf[p][3]);
            }
        }

        // P = exp2(S): ONE MUFU per packed pair; hp words are PV A-frags.
        uint32_t hp01[8], hp23[8];
#pragma unroll
        for (int nb = 0; nb < 8; nb++) {
            hp01[nb] = h2ex2(packh2(c_[nb][0], c_[nb][1]));
            hp23[nb] = h2ex2(packh2(c_[nb][2], c_[nb][3]));
            float2 f0 = __half22float2(*(__half2*)&hp01[nb]);
            float2 f1 = __half22float2(*(__half2*)&hp23[nb]);
            l0 += f0.x + f0.y;
            l1 += f1.x + f1.y;
        }

        // O += P V
#pragma unroll
        for (int g = 0; g < 4; g++) {
            uint32_t aP[4] = { hp01[2 * g], hp23[2 * g],
                               hp01[2 * g + 1], hp23[2 * g + 1] };
            uint32_t bf[4][4];
#pragma unroll
            for (int p = 0; p < 4; p++)
                ldsm4(bf[p][0], bf[p][1], bf[p][2], bf[p][3],
                      vbase + (p * 16 * KSTRH + g * 16) * 2);
#pragma unroll
            for (int p = 0; p < 4; p++) {
                mma16(o[2 * p], aP, bf[p][0], bf[p][1]);
                mma16(o[2 * p + 1], aP, bf[p][2], bf[p][3]);
            }
        }
    }

    // one-shot denominator reduction across the quad
#pragma unroll
    for (int off = 1; off <= 2; off <<= 1) {
        l0 += __shfl_xor_sync(FULLM, l0, off);
        l1 += __shfl_xor_sync(FULLM, l1, off);
    }
    const float inv0 = 1.0f / l0, inv1 = 1.0f / l1;
#pragma unroll
    for (int nb = 0; nb < 8; nb++) {
        size_t base = headOff + (size_t)(q0 + wm + gq) * EMB + nb * 8 + 2 * tq;
        *(uint32_t*)(O + base) = packh2(o[nb][0] * inv0, o[nb][1] * inv0);
        *(uint32_t*)(O + base + (size_t)8 * EMB) =
            packh2(o[nb][2] * inv1, o[nb][3] * inv1);
    }
}

// ---------------------------------------------------------------------------
// Output GEMM: Y(4096x1024) fp32 = X @ Wo^T + bo.  BM=128, BN=128, BK=64.
// 3-stage ring, one barrier per k-tile, ldmatrix.x4 loads.  grid=256, 8 warps.
// ---------------------------------------------------------------------------
#define OSTRH 72
#define XELEH (128 * OSTRH)
#define OSTAGEH (2 * XELEH)
#define NKT (EMB / 64)

extern __shared__ __half og_smem[];

__global__ __launch_bounds__(256) void out_tc(const __half* __restrict__ X,
                                              const __half* __restrict__ W,
                                              const float* __restrict__ bias,
                                              float* __restrict__ Y) {
    __half* smem = og_smem;
    const int t = threadIdx.x, lane = t & 31, warp = t >> 5;
    const int tq = lane & 3, gq = lane >> 2;
    const int wm = warp * 16;
    const int lrow = lane & 7, lmat = lane >> 3;
    const int m0 = blockIdx.x * 128, n0 = blockIdx.y * 128;
    const uint32_t sb = (uint32_t)__cvta_generic_to_shared(smem);
    const uint32_t lanoffA =
        (uint32_t)((((lmat & 1) * 8 + lrow) * OSTRH + (lmat >> 1) * 8) * 2);
    const uint32_t lanoffB =
        (uint32_t)((((lmat >> 1) * 8 + lrow) * OSTRH + (lmat & 1) * 8) * 2);

#pragma unroll
    for (int pre = 0; pre < 2; pre++) {
        const int k0 = pre * 64;
        const uint32_t dst = sb + pre * OSTAGEH * 2;
#pragma unroll
        for (int i = 0; i < 4; i++) {
            int id = i * 256 + t;
            int r = id >> 3, c = (id & 7) << 3;
            cpa16(dst + (r * OSTRH + c) * 2, X + (size_t)(m0 + r) * EMB + k0 + c);
            cpa16(dst + (XELEH + r * OSTRH + c) * 2,
                  W + (size_t)(n0 + r) * EMB + k0 + c);
        }
        cpa_commit();
    }

    float acc[16][4] = {};
    int bufc = 0;
    for (int kt = 0; kt < NKT; kt++) {
        if (kt + 1 < NKT) {
            asm volatile("cp.async.wait_group 1;");
        } else {
            asm volatile("cp.async.wait_group 0;");
        }
        __syncthreads();

        if (kt + 2 < NKT) {
            const int k0 = (kt + 2) * 64;
            int bufp = bufc + 2; if (bufp >= NSTG) bufp -= NSTG;
            const uint32_t dst = sb + bufp * OSTAGEH * 2;
#pragma unroll
            for (int i = 0; i < 4; i++) {
                int id = i * 256 + t;
                int r = id >> 3, c = (id & 7) << 3;
                cpa16(dst + (r * OSTRH + c) * 2, X + (size_t)(m0 + r) * EMB + k0 + c);
                cpa16(dst + (XELEH + r * OSTRH + c) * 2,
                      W + (size_t)(n0 + r) * EMB + k0 + c);
            }
            cpa_commit();
        }

        const uint32_t xbase = sb + bufc * (OSTAGEH * 2) +
                               (uint32_t)(wm * OSTRH * 2) + lanoffA;
        const uint32_t wbase = sb + bufc * (OSTAGEH * 2) + XELEH * 2 + lanoffB;
        bufc = (bufc + 1 < NSTG) ? bufc + 1 : 0;
#pragma unroll
        for (int kg = 0; kg < 4; kg++) {
            uint32_t a[4];
            ldsm4(a[0], a[1], a[2], a[3], xbase + kg * 32);
#pragma unroll
            for (int p = 0; p < 8; p++) {
                uint32_t r0, r1, r2, r3;
                ldsm4(r0, r1, r2, r3, wbase + (p * 16 * OSTRH + kg * 16) * 2);
                mma16(acc[2 * p], a, r0, r1);
                mma16(acc[2 * p + 1], a, r2, r3);
            }
        }
    }

#pragma unroll
    for (int nb = 0; nb < 16; nb++) {
        int col = n0 + nb * 8 + 2 * tq;
        float b0 = __ldg(bias + col), b1 = __ldg(bias + col + 1);
        size_t base = (size_t)(m0 + wm + gq) * EMB + col;
        *(float2*)(Y + base) = make_float2(acc[nb][0] + b0, acc[nb][1] + b1);
        *(float2*)(Y + base + (size_t)8 * EMB) =
            make_float2(acc[nb][2] + b0, acc[nb][3] + b1);
    }
}

// ---------------------------------------------------------------------------
extern "C" void kernel_launch(void* const* d_in, const int* in_sizes, int n_in,
                              void* d_out, int out_size) {
    const float* q  = (const float*)d_in[0];
    const float* k  = (const float*)d_in[1];
    const float* v  = (const float*)d_in[2];
    const float* Wq = (const float*)d_in[3];
    const float* Wk = (const float*)d_in[4];
    const float* Wv = (const float*)d_in[5];
    const float* Wo = (const float*)d_in[6];
    const float* bo = (const float*)d_in[7];
    float* out = (float*)d_out;

    __half *qp, *kp, *vp, *vt, *ao, *wo;
    cudaGetSymbolAddress((void**)&qp, g_qp);
    cudaGetSymbolAddress((void**)&kp, g_kp);
    cudaGetSymbolAddress((void**)&vp, g_vp);
    cudaGetSymbolAddress((void**)&vt, g_vt);
    cudaGetSymbolAddress((void**)&ao, g_ao);
    cudaGetSymbolAddress((void**)&wo, g_wo);

    static bool attr_done = false;
    if (!attr_done) {
        cudaFuncSetAttribute(flash_tc, cudaFuncAttributeMaxDynamicSharedMemorySize,
                             NSTG * STAGEH * 2);
        cudaFuncSetAttribute(out_tc, cudaFuncAttributeMaxDynamicSharedMemorySize,
                             NSTG * OSTAGEH * 2);
        attr_done = true;
    }

    cvt_wo<<<1024, 256>>>(Wo, wo);
    proj_tc<<<dim3(1024, 3), 128>>>(q, k, v, Wq, Wk, Wv, qp, kp, vp);
    transp_v<<<dim3(S_LEN / 64, N_B * HEADS), 256>>>(vp, vt);
    flash_tc<<<dim3(S_LEN / 128, N_B * HEADS), 256, NSTG * STAGEH * 2>>>(qp, kp, vt, ao);
    out_tc<<<dim3((N_B * S_LEN) / 128, EMB / 128), 256, NSTG * OSTAGEH * 2>>>(ao, wo, bo, out);
}

// round 12
// speedup vs baseline: 1.1208x; 1.0162x over previous
#include <cuda_runtime.h>
#include <cuda_fp16.h>
#include <cstdint>
#include <cstddef>

#define N_B   2
#define S_LEN 2048
#define HEADS 16
#define HDIM  64
#define EMB   1024
// 1/sqrt(1024) * log2(e): softmax runs in exp2 domain
#define QSCALE (0.03125f * 1.44269504088896340736f)
#define FULLM 0xffffffffu

// Scratch (alloc-free rule: __device__ globals), fp16.
__device__ __half g_qp[N_B * S_LEN * EMB];
__device__ __half g_kp[N_B * S_LEN * EMB];
__device__ __half g_vp[N_B * S_LEN * EMB];   // (n,s,h,d) projected V
__device__ __half g_vt[N_B * HEADS * HDIM * S_LEN]; // (n,h,d,s) transposed V
__device__ __half g_ao[N_B * S_LEN * EMB];
__device__ __half g_wo[EMB * EMB];

__device__ __forceinline__ uint32_t packh2(float lo, float hi) {
    __half2 h = __floats2half2_rn(lo, hi);
    return *(uint32_t*)&h;
}
// exp2 on a packed half2 (one MUFU op for two values)
__device__ __forceinline__ uint32_t h2ex2(uint32_t x) {
    uint32_t r;
    asm("ex2.approx.f16x2 %0, %1;" : "=r"(r) : "r"(x));
    return r;
}
#define LDU32(p) (*(const uint32_t*)(p))

// D(16x8) += A(16x16)*B(16x8), fp16 in, fp32 accum.
__device__ __forceinline__ void mma16(float* c, const uint32_t* a,
                                      uint32_t b0, uint32_t b1) {
    asm volatile(
        "mma.sync.aligned.m16n8k16.row.col.f32.f16.f16.f32 "
        "{%0,%1,%2,%3},{%4,%5,%6,%7},{%8,%9},{%0,%1,%2,%3};"
        : "+f"(c[0]), "+f"(c[1]), "+f"(c[2]), "+f"(c[3])
        : "r"(a[0]), "r"(a[1]), "r"(a[2]), "r"(a[3]), "r"(b0), "r"(b1));
}

// 4x 8x8 b16 fragments in one shot, mma-ready layout
__device__ __forceinline__ void ldsm4(uint32_t& r0, uint32_t& r1,
                                      uint32_t& r2, uint32_t& r3, uint32_t a) {
    asm volatile("ldmatrix.sync.aligned.m8n8.x4.shared.b16 {%0,%1,%2,%3}, [%4];"
                 : "=r"(r0), "=r"(r1), "=r"(r2), "=r"(r3) : "r"(a));
}

__device__ __forceinline__ void cpa16(uint32_t s, const void* g) {
    asm volatile("cp.async.ca.shared.global [%0], [%1], 16;" :: "r"(s), "l"(g));
}
__device__ __forceinline__ void cpa_commit() {
    asm volatile("cp.async.commit_group;");
}

// ---------------------------------------------------------------------------
// Wo fp32 -> fp16
// ---------------------------------------------------------------------------
__global__ __launch_bounds__(256) void cvt_wo(const float* __restrict__ W,
                                              __half* __restrict__ Y) {
    int i = (blockIdx.x * 256 + threadIdx.x) * 4;
    float4 v = *(const float4*)(W + i);
    uint2 o = make_uint2(packh2(v.x, v.y), packh2(v.z, v.w));
    *(uint2*)(Y + i) = o;
}

// ---------------------------------------------------------------------------
// Projection: Y(65536x64) fp16 = rn_h((X @ W^T) * sc).  Q gets QSCALE.
// ---------------------------------------------------------------------------
#define PSTR 72
__global__ __launch_bounds__(128) void proj_tc(const float* __restrict__ xq,
                                               const float* __restrict__ xk,
                                               const float* __restrict__ xv,
                                               const float* __restrict__ wq,
                                               const float* __restrict__ wk,
                                               const float* __restrict__ wv,
                                               __half* __restrict__ yq,
                                               __half* __restrict__ yk,
                                               __half* __restrict__ yv) {
    __shared__ __half Xs[64 * PSTR];
    __shared__ __half Ws[64 * PSTR];
    const int t = threadIdx.x, lane = t & 31, warp = t >> 5;
    const int tq = lane & 3, gq = lane >> 2;
    const int wm = warp * 16;
    const int rowBase = blockIdx.x * 64;
    const int which = blockIdx.y;
    const float* X = (which == 0) ? xq : (which == 1) ? xk : xv;
    const float* W = (which == 0) ? wq : (which == 1) ? wk : wv;
    __half* Y = (which == 0) ? yq : (which == 1) ? yk : yv;
    const float sc = (which == 0) ? QSCALE : 1.0f;

#pragma unroll
    for (int i = 0; i < 8; i++) {
        int idx = i * 128 + t;
        int r = idx >> 4, c = (idx & 15) << 2;
        float4 v = *(const float4*)(X + (size_t)(rowBase + r) * 64 + c);
        *(uint2*)(&Xs[r * PSTR + c]) = make_uint2(packh2(v.x, v.y), packh2(v.z, v.w));
        float4 w = *(const float4*)(W + r * 64 + c);
        *(uint2*)(&Ws[r * PSTR + c]) = make_uint2(packh2(w.x, w.y), packh2(w.z, w.w));
    }
    __syncthreads();

    float c[8][4] = {};
#pragma unroll
    for (int kg = 0; kg < 4; kg++) {
        const int kk = kg * 16 + 2 * tq;
        uint32_t a[4] = { LDU32(&Xs[(wm + gq) * PSTR + kk]),
                          LDU32(&Xs[(wm + gq + 8) * PSTR + kk]),
                          LDU32(&Xs[(wm + gq) * PSTR + kk + 8]),
                          LDU32(&Xs[(wm + gq + 8) * PSTR + kk + 8]) };
        uint32_t b0[8], b1[8];
#pragma unroll
        for (int nb = 0; nb < 8; nb++) {
            b0[nb] = LDU32(&Ws[(nb * 8 + gq) * PSTR + kk]);
            b1[nb] = LDU32(&Ws[(nb * 8 + gq) * PSTR + kk + 8]);
        }
#pragma unroll
        for (int nb = 0; nb < 8; nb++) mma16(c[nb], a, b0[nb], b1[nb]);
    }
#pragma unroll
    for (int nb = 0; nb < 8; nb++) {
        size_t base = (size_t)(rowBase + wm + gq) * 64 + nb * 8 + 2 * tq;
        *(uint32_t*)(Y + base) = packh2(c[nb][0] * sc, c[nb][1] * sc);
        *(uint32_t*)(Y + base + 8 * 64) = packh2(c[nb][2] * sc, c[nb][3] * sc);
    }
}

// ---------------------------------------------------------------------------
// V transpose: vp (n,s,h,d) -> vt (n,h,d,s).
// ---------------------------------------------------------------------------
__global__ __launch_bounds__(256) void transp_v(const __half* __restrict__ vp,
                                                __half* __restrict__ vt) {
    __shared__ __half Ts[64][66];
    const int t = threadIdx.x;
    const int s0 = blockIdx.x * 64;
    const int nh = blockIdx.y;
    const int n = nh >> 4, h = nh & 15;
    const __half* src = vp + ((size_t)n * S_LEN * HEADS + h) * HDIM;
#pragma unroll
    for (int i = 0; i < 8; i++) {
        int id = i * 256 + t;
        int r = id >> 5;
        int c = (id & 31) * 2;
        __half2 v = *(const __half2*)(src + (size_t)(s0 + r) * EMB + c);
        Ts[c][r] = v.x;
        Ts[c + 1][r] = v.y;
    }
    __syncthreads();
    __half* dst = vt + (size_t)nh * HDIM * S_LEN;
#pragma unroll
    for (int i = 0; i < 8; i++) {
        int id = i * 256 + t;
        int d = id >> 5;
        int s = (id & 31) * 2;
        __half2 v;
        v.x = Ts[d][s];
        v.y = Ts[d][s + 1];
        *(__half2*)(dst + (size_t)d * S_LEN + s0 + s) = v;
    }
}

// ---------------------------------------------------------------------------
// Flash attention fp16: fixed-max exp2 softmax (f16x2 MUFU), ldmatrix.x4,
// 2-stage ring with ONE barrier per tile (order: wait -> barrier -> prefetch
// kt+1 into the buffer tile kt-1 just vacated -> compute kt).
// smem 36.9 KB -> all 512 blocks resident in a single wave.
// grid=(S/128, N*H), 256 thr = 8 warps, BM=128, BN=64.
// ---------------------------------------------------------------------------
#define KSTRH 72
#define KELEH (64 * KSTRH)
#define STAGEH (2 * KELEH)      // K tile + V tile (halves)
#define NT (S_LEN / 64)

extern __shared__ __half fa_smem[];

__global__ __launch_bounds__(256) void flash_tc(const __half* __restrict__ Q,
                                                const __half* __restrict__ K,
                                                const __half* __restrict__ Vt,
                                                __half* __restrict__ O) {
    __half* smem = fa_smem;
    const int t = threadIdx.x, lane = t & 31, warp = t >> 5;
    const int tq = lane & 3, gq = lane >> 2;
    const int wm = warp * 16;
    const int lrow = lane & 7, lmat = lane >> 3;
    const int qt = blockIdx.x, nh = blockIdx.y;
    const int n = nh >> 4, h = nh & 15;
    const size_t headOff = ((size_t)n * S_LEN * HEADS + h) * HDIM;
    const __half* qb = Q + headOff;
    const __half* kb = K + headOff;
    const __half* vtb = Vt + (size_t)nh * HDIM * S_LEN;
    const int q0 = qt * 128;
    const uint32_t sb = (uint32_t)__cvta_generic_to_shared(smem);
    // per-lane invariant offset for B-fragment ldmatrix (bytes)
    const uint32_t lanoffB =
        (uint32_t)((((lmat >> 1) * 8 + lrow) * KSTRH + (lmat & 1) * 8) * 2);

    // stage Q tile (128x64 halves) into buffer 0, pull A-frags into regs
#pragma unroll
    for (int i = 0; i < 4; i++) {
        int id = i * 256 + t;
        int r = id >> 3, c = (id & 7) << 3;
        cpa16(sb + (r * KSTRH + c) * 2, qb + (size_t)(q0 + r) * EMB + c);
    }
    cpa_commit();
    asm volatile("cp.async.wait_group 0;");
    __syncthreads();
    uint32_t aQ[4][4];
    {
        const uint32_t lanoffA =
            (uint32_t)((((lmat & 1) * 8 + lrow) * KSTRH + (lmat >> 1) * 8) * 2);
#pragma unroll
        for (int kg = 0; kg < 4; kg++)
            ldsm4(aQ[kg][0], aQ[kg][1], aQ[kg][2], aQ[kg][3],
                  sb + (uint32_t)(wm * KSTRH * 2) + lanoffA + kg * 32);
    }
    __syncthreads();

    // prologue: prefetch tile 0 into buffer 0
    {
#pragma unroll
        for (int i = 0; i < 2; i++) {
            int id = i * 256 + t;
            int r = id >> 3, c = (id & 7) << 3;
            cpa16(sb + (r * KSTRH + c) * 2, kb + (size_t)r * EMB + c);
            cpa16(sb + (KELEH + r * KSTRH + c) * 2, vtb + (size_t)r * S_LEN + c);
        }
        cpa_commit();
    }

    float o[8][4] = {};
    float l0 = 0.f, l1 = 0.f;
    int bufc = 0;

    for (int kt = 0; kt < NT; kt++) {
        asm volatile("cp.async.wait_group 0;");  // tile kt landed
        __syncthreads();                         // all warps done with kt-1

        if (kt + 1 < NT) {                       // prefetch kt+1 into buf^1
            const int k0 = (kt + 1) * 64;
            const uint32_t dst = sb + (bufc ^ 1) * (STAGEH * 2);
#pragma unroll
            for (int i = 0; i < 2; i++) {
                int id = i * 256 + t;
                int r = id >> 3, c = (id & 7) << 3;
                cpa16(dst + (r * KSTRH + c) * 2, kb + (size_t)(k0 + r) * EMB + c);
                cpa16(dst + (KELEH + r * KSTRH + c) * 2,
                      vtb + (size_t)r * S_LEN + k0 + c);
            }
            cpa_commit();
        }

        const uint32_t kbase = sb + bufc * (STAGEH * 2) + lanoffB;
        const uint32_t vbase = kbase + KELEH * 2;
        bufc ^= 1;

        // S = Q K^T (log2e-scale baked into Q); B-frags via ldmatrix.x4
        float c_[8][4] = {};
#pragma unroll
        for (int kg = 0; kg < 4; kg++) {
            uint32_t bf[4][4];
#pragma unroll
            for (int p = 0; p < 4; p++)
                ldsm4(bf[p][0], bf[p][1], bf[p][2], bf[p][3],
                      kbase + (p * 16 * KSTRH + kg * 16) * 2);
#pragma unroll
            for (int p = 0; p < 4; p++) {
                mma16(c_[2 * p], aQ[kg], bf[p][0], bf[p][1]);
                mma16(c_[2 * p + 1], aQ[kg], bf[p][2], bf[p][3]);
            }
        }

        // P = exp2(S): ONE MUFU per packed pair; hp words are PV A-frags.
        uint32_t hp01[8], hp23[8];
#pragma unroll
        for (int nb = 0; nb < 8; nb++) {
            hp01[nb] = h2ex2(packh2(c_[nb][0], c_[nb][1]));
            hp23[nb] = h2ex2(packh2(c_[nb][2], c_[nb][3]));
            float2 f0 = __half22float2(*(__half2*)&hp01[nb]);
            float2 f1 = __half22float2(*(__half2*)&hp23[nb]);
            l0 += f0.x + f0.y;
            l1 += f1.x + f1.y;
        }

        // O += P V
#pragma unroll
        for (int g = 0; g < 4; g++) {
            uint32_t aP[4] = { hp01[2 * g], hp23[2 * g],
                               hp01[2 * g + 1], hp23[2 * g + 1] };
            uint32_t bf[4][4];
#pragma unroll
            for (int p = 0; p < 4; p++)
                ldsm4(bf[p][0], bf[p][1], bf[p][2], bf[p][3],
                      vbase + (p * 16 * KSTRH + g * 16) * 2);
#pragma unroll
            for (int p = 0; p < 4; p++) {
                mma16(o[2 * p], aP, bf[p][0], bf[p][1]);
                mma16(o[2 * p + 1], aP, bf[p][2], bf[p][3]);
            }
        }
    }

    // one-shot denominator reduction across the quad
#pragma unroll
    for (int off = 1; off <= 2; off <<= 1) {
        l0 += __shfl_xor_sync(FULLM, l0, off);
        l1 += __shfl_xor_sync(FULLM, l1, off);
    }
    const float inv0 = 1.0f / l0, inv1 = 1.0f / l1;
#pragma unroll
    for (int nb = 0; nb < 8; nb++) {
        size_t base = headOff + (size_t)(q0 + wm + gq) * EMB + nb * 8 + 2 * tq;
        *(uint32_t*)(O + base) = packh2(o[nb][0] * inv0, o[nb][1] * inv0);
        *(uint32_t*)(O + base + (size_t)8 * EMB) =
            packh2(o[nb][2] * inv1, o[nb][3] * inv1);
    }
}

// ---------------------------------------------------------------------------
// Output GEMM: Y(4096x1024) fp32 = X @ Wo^T + bo.  BM=128, BN=128, BK=64.
// 2-stage ring, one barrier per k-tile, ldmatrix.x4.  grid=256, 8 warps.
// ---------------------------------------------------------------------------
#define OSTRH 72
#define XELEH (128 * OSTRH)
#define OSTAGEH (2 * XELEH)
#define NKT (EMB / 64)

extern __shared__ __half og_smem[];

__global__ __launch_bounds__(256) void out_tc(const __half* __restrict__ X,
                                              const __half* __restrict__ W,
                                              const float* __restrict__ bias,
                                              float* __restrict__ Y) {
    __half* smem = og_smem;
    const int t = threadIdx.x, lane = t & 31, warp = t >> 5;
    const int tq = lane & 3, gq = lane >> 2;
    const int wm = warp * 16;
    const int lrow = lane & 7, lmat = lane >> 3;
    const int m0 = blockIdx.x * 128, n0 = blockIdx.y * 128;
    const uint32_t sb = (uint32_t)__cvta_generic_to_shared(smem);
    const uint32_t lanoffA =
        (uint32_t)((((lmat & 1) * 8 + lrow) * OSTRH + (lmat >> 1) * 8) * 2);
    const uint32_t lanoffB =
        (uint32_t)((((lmat >> 1) * 8 + lrow) * OSTRH + (lmat & 1) * 8) * 2);

    // prologue: prefetch k-tile 0 into buffer 0
    {
#pragma unroll
        for (int i = 0; i < 4; i++) {
            int id = i * 256 + t;
            int r = id >> 3, c = (id & 7) << 3;
            cpa16(sb + (r * OSTRH + c) * 2, X + (size_t)(m0 + r) * EMB + c);
            cpa16(sb + (XELEH + r * OSTRH + c) * 2, W + (size_t)(n0 + r) * EMB + c);
        }
        cpa_commit();
    }

    float acc[16][4] = {};
    int bufc = 0;
    for (int kt = 0; kt < NKT; kt++) {
        asm volatile("cp.async.wait_group 0;");
        __syncthreads();

        if (kt + 1 < NKT) {
            const int k0 = (kt + 1) * 64;
            const uint32_t dst = sb + (bufc ^ 1) * (OSTAGEH * 2);
#pragma unroll
            for (int i = 0; i < 4; i++) {
                int id = i * 256 + t;
                int r = id >> 3, c = (id & 7) << 3;
                cpa16(dst + (r * OSTRH + c) * 2, X + (size_t)(m0 + r) * EMB + k0 + c);
                cpa16(dst + (XELEH + r * OSTRH + c) * 2,
                      W + (size_t)(n0 + r) * EMB + k0 + c);
            }
            cpa_commit();
        }

        const uint32_t xbase = sb + bufc * (OSTAGEH * 2) +
                               (uint32_t)(wm * OSTRH * 2) + lanoffA;
        const uint32_t wbase = sb + bufc * (OSTAGEH * 2) + XELEH * 2 + lanoffB;
        bufc ^= 1;
#pragma unroll
        for (int kg = 0; kg < 4; kg++) {
            uint32_t a[4];
            ldsm4(a[0], a[1], a[2], a[3], xbase + kg * 32);
#pragma unroll
            for (int p = 0; p < 8; p++) {
                uint32_t r0, r1, r2, r3;
                ldsm4(r0, r1, r2, r3, wbase + (p * 16 * OSTRH + kg * 16) * 2);
                mma16(acc[2 * p], a, r0, r1);
                mma16(acc[2 * p + 1], a, r2, r3);
            }
        }
    }

#pragma unroll
    for (int nb = 0; nb < 16; nb++) {
        int col = n0 + nb * 8 + 2 * tq;
        float b0 = __ldg(bias + col), b1 = __ldg(bias + col + 1);
        size_t base = (size_t)(m0 + wm + gq) * EMB + col;
        *(float2*)(Y + base) = make_float2(acc[nb][0] + b0, acc[nb][1] + b1);
        *(float2*)(Y + base + (size_t)8 * EMB) =
            make_float2(acc[nb][2] + b0, acc[nb][3] + b1);
    }
}

// ---------------------------------------------------------------------------
extern "C" void kernel_launch(void* const* d_in, const int* in_sizes, int n_in,
                              void* d_out, int out_size) {
    const float* q  = (const float*)d_in[0];
    const float* k  = (const float*)d_in[1];
    const float* v  = (const float*)d_in[2];
    const float* Wq = (const float*)d_in[3];
    const float* Wk = (const float*)d_in[4];
    const float* Wv = (const float*)d_in[5];
    const float* Wo = (const float*)d_in[6];
    const float* bo = (const float*)d_in[7];
    float* out = (float*)d_out;

    __half *qp, *kp, *vp, *vt, *ao, *wo;
    cudaGetSymbolAddress((void**)&qp, g_qp);
    cudaGetSymbolAddress((void**)&kp, g_kp);
    cudaGetSymbolAddress((void**)&vp, g_vp);
    cudaGetSymbolAddress((void**)&vt, g_vt);
    cudaGetSymbolAddress((void**)&ao, g_ao);
    cudaGetSymbolAddress((void**)&wo, g_wo);

    static bool attr_done = false;
    if (!attr_done) {
        cudaFuncSetAttribute(flash_tc, cudaFuncAttributeMaxDynamicSharedMemorySize,
                             2 * STAGEH * 2);
        cudaFuncSetAttribute(out_tc, cudaFuncAttributeMaxDynamicSharedMemorySize,
                             2 * OSTAGEH * 2);
        attr_done = true;
    }

    cvt_wo<<<1024, 256>>>(Wo, wo);
    proj_tc<<<dim3(1024, 3), 128>>>(q, k, v, Wq, Wk, Wv, qp, kp, vp);
    transp_v<<<dim3(S_LEN / 64, N_B * HEADS), 256>>>(vp, vt);
    flash_tc<<<dim3(S_LEN / 128, N_B * HEADS), 256, 2 * STAGEH * 2>>>(qp, kp, vt, ao);
    out_tc<<<dim3((N_B * S_LEN) / 128, EMB / 128), 256, 2 * OSTAGEH * 2>>>(ao, wo, bo, out);
}

// round 13
// speedup vs baseline: 1.1315x; 1.0095x over previous
#include <cuda_runtime.h>
#include <cuda_fp16.h>
#include <cstdint>
#include <cstddef>

#define N_B   2
#define S_LEN 2048
#define HEADS 16
#define HDIM  64
#define EMB   1024
// 1/sqrt(1024) * log2(e): softmax runs in exp2 domain
#define QSCALE (0.03125f * 1.44269504088896340736f)
#define FULLM 0xffffffffu

// Scratch (alloc-free rule: __device__ globals), fp16.
__device__ __half g_qp[N_B * S_LEN * EMB];
__device__ __half g_kp[N_B * S_LEN * EMB];
__device__ __half g_vp[N_B * S_LEN * EMB];   // (n,s,h,d) projected V
__device__ __half g_vt[N_B * HEADS * HDIM * S_LEN]; // (n,h,d,s) transposed V
__device__ __half g_ao[N_B * S_LEN * EMB];
__device__ __half g_wo[EMB * EMB];

__device__ __forceinline__ uint32_t packh2(float lo, float hi) {
    __half2 h = __floats2half2_rn(lo, hi);
    return *(uint32_t*)&h;
}
// exp2 on a packed half2 (one MUFU op for two values)
__device__ __forceinline__ uint32_t h2ex2(uint32_t x) {
    uint32_t r;
    asm("ex2.approx.f16x2 %0, %1;" : "=r"(r) : "r"(x));
    return r;
}
#define LDU32(p) (*(const uint32_t*)(p))

// D(16x8) += A(16x16)*B(16x8), fp16 in, fp32 accum.
__device__ __forceinline__ void mma16(float* c, const uint32_t* a,
                                      uint32_t b0, uint32_t b1) {
    asm volatile(
        "mma.sync.aligned.m16n8k16.row.col.f32.f16.f16.f32 "
        "{%0,%1,%2,%3},{%4,%5,%6,%7},{%8,%9},{%0,%1,%2,%3};"
        : "+f"(c[0]), "+f"(c[1]), "+f"(c[2]), "+f"(c[3])
        : "r"(a[0]), "r"(a[1]), "r"(a[2]), "r"(a[3]), "r"(b0), "r"(b1));
}

// 4x 8x8 b16 fragments in one shot, mma-ready layout
__device__ __forceinline__ void ldsm4(uint32_t& r0, uint32_t& r1,
                                      uint32_t& r2, uint32_t& r3, uint32_t a) {
    asm volatile("ldmatrix.sync.aligned.m8n8.x4.shared.b16 {%0,%1,%2,%3}, [%4];"
                 : "=r"(r0), "=r"(r1), "=r"(r2), "=r"(r3) : "r"(a));
}

__device__ __forceinline__ void cpa16(uint32_t s, const void* g) {
    asm volatile("cp.async.ca.shared.global [%0], [%1], 16;" :: "r"(s), "l"(g));
}
__device__ __forceinline__ void cpa_commit() {
    asm volatile("cp.async.commit_group;");
}

// ---------------------------------------------------------------------------
// Wo fp32 -> fp16
// ---------------------------------------------------------------------------
__global__ __launch_bounds__(256) void cvt_wo(const float* __restrict__ W,
                                              __half* __restrict__ Y) {
    int i = (blockIdx.x * 256 + threadIdx.x) * 4;
    float4 v = *(const float4*)(W + i);
    uint2 o = make_uint2(packh2(v.x, v.y), packh2(v.z, v.w));
    *(uint2*)(Y + i) = o;
}

// ---------------------------------------------------------------------------
// Projection: Y(65536x64) fp16 = rn_h((X @ W^T) * sc).  Q gets QSCALE.
// ---------------------------------------------------------------------------
#define PSTR 72
__global__ __launch_bounds__(128) void proj_tc(const float* __restrict__ xq,
                                               const float* __restrict__ xk,
                                               const float* __restrict__ xv,
                                               const float* __restrict__ wq,
                                               const float* __restrict__ wk,
                                               const float* __restrict__ wv,
                                               __half* __restrict__ yq,
                                               __half* __restrict__ yk,
                                               __half* __restrict__ yv) {
    __shared__ __half Xs[64 * PSTR];
    __shared__ __half Ws[64 * PSTR];
    const int t = threadIdx.x, lane = t & 31, warp = t >> 5;
    const int tq = lane & 3, gq = lane >> 2;
    const int wm = warp * 16;
    const int rowBase = blockIdx.x * 64;
    const int which = blockIdx.y;
    const float* X = (which == 0) ? xq : (which == 1) ? xk : xv;
    const float* W = (which == 0) ? wq : (which == 1) ? wk : wv;
    __half* Y = (which == 0) ? yq : (which == 1) ? yk : yv;
    const float sc = (which == 0) ? QSCALE : 1.0f;

#pragma unroll
    for (int i = 0; i < 8; i++) {
        int idx = i * 128 + t;
        int r = idx >> 4, c = (idx & 15) << 2;
        float4 v = *(const float4*)(X + (size_t)(rowBase + r) * 64 + c);
        *(uint2*)(&Xs[r * PSTR + c]) = make_uint2(packh2(v.x, v.y), packh2(v.z, v.w));
        float4 w = *(const float4*)(W + r * 64 + c);
        *(uint2*)(&Ws[r * PSTR + c]) = make_uint2(packh2(w.x, w.y), packh2(w.z, w.w));
    }
    __syncthreads();

    float c[8][4] = {};
#pragma unroll
    for (int kg = 0; kg < 4; kg++) {
        const int kk = kg * 16 + 2 * tq;
        uint32_t a[4] = { LDU32(&Xs[(wm + gq) * PSTR + kk]),
                          LDU32(&Xs[(wm + gq + 8) * PSTR + kk]),
                          LDU32(&Xs[(wm + gq) * PSTR + kk + 8]),
                          LDU32(&Xs[(wm + gq + 8) * PSTR + kk + 8]) };
        uint32_t b0[8], b1[8];
#pragma unroll
        for (int nb = 0; nb < 8; nb++) {
            b0[nb] = LDU32(&Ws[(nb * 8 + gq) * PSTR + kk]);
            b1[nb] = LDU32(&Ws[(nb * 8 + gq) * PSTR + kk + 8]);
        }
#pragma unroll
        for (int nb = 0; nb < 8; nb++) mma16(c[nb], a, b0[nb], b1[nb]);
    }
#pragma unroll
    for (int nb = 0; nb < 8; nb++) {
        size_t base = (size_t)(rowBase + wm + gq) * 64 + nb * 8 + 2 * tq;
        *(uint32_t*)(Y + base) = packh2(c[nb][0] * sc, c[nb][1] * sc);
        *(uint32_t*)(Y + base + 8 * 64) = packh2(c[nb][2] * sc, c[nb][3] * sc);
    }
}

// ---------------------------------------------------------------------------
// V transpose: vp (n,s,h,d) -> vt (n,h,d,s).
// ---------------------------------------------------------------------------
__global__ __launch_bounds__(256) void transp_v(const __half* __restrict__ vp,
                                                __half* __restrict__ vt) {
    __shared__ __half Ts[64][66];
    const int t = threadIdx.x;
    const int s0 = blockIdx.x * 64;
    const int nh = blockIdx.y;
    const int n = nh >> 4, h = nh & 15;
    const __half* src = vp + ((size_t)n * S_LEN * HEADS + h) * HDIM;
#pragma unroll
    for (int i = 0; i < 8; i++) {
        int id = i * 256 + t;
        int r = id >> 5;
        int c = (id & 31) * 2;
        __half2 v = *(const __half2*)(src + (size_t)(s0 + r) * EMB + c);
        Ts[c][r] = v.x;
        Ts[c + 1][r] = v.y;
    }
    __syncthreads();
    __half* dst = vt + (size_t)nh * HDIM * S_LEN;
#pragma unroll
    for (int i = 0; i < 8; i++) {
        int id = i * 256 + t;
        int d = id >> 5;
        int s = (id & 31) * 2;
        __half2 v;
        v.x = Ts[d][s];
        v.y = Ts[d][s + 1];
        *(__half2*)(dst + (size_t)d * S_LEN + s0 + s) = v;
    }
}

// ---------------------------------------------------------------------------
// Flash attention fp16: per-key-group interleaved QK->exp2->PV (shrinks live
// registers: full 8x4 score block never resident), fixed-max exp2 softmax,
// ldmatrix.x4, 2-stage ring w/ one barrier per tile, 3 blocks/SM forced.
// grid=(S/128, N*H), 256 thr = 8 warps, BM=128, BN=64.
// ---------------------------------------------------------------------------
#define KSTRH 72
#define KELEH (64 * KSTRH)
#define STAGEH (2 * KELEH)      // K tile + V tile (halves)
#define NT (S_LEN / 64)

extern __shared__ __half fa_smem[];

__global__ __launch_bounds__(256, 3) void flash_tc(const __half* __restrict__ Q,
                                                   const __half* __restrict__ K,
                                                   const __half* __restrict__ Vt,
                                                   __half* __restrict__ O) {
    __half* smem = fa_smem;
    const int t = threadIdx.x, lane = t & 31, warp = t >> 5;
    const int tq = lane & 3, gq = lane >> 2;
    const int wm = warp * 16;
    const int lrow = lane & 7, lmat = lane >> 3;
    const int qt = blockIdx.x, nh = blockIdx.y;
    const int n = nh >> 4, h = nh & 15;
    const size_t headOff = ((size_t)n * S_LEN * HEADS + h) * HDIM;
    const __half* qb = Q + headOff;
    const __half* kb = K + headOff;
    const __half* vtb = Vt + (size_t)nh * HDIM * S_LEN;
    const int q0 = qt * 128;
    const uint32_t sb = (uint32_t)__cvta_generic_to_shared(smem);
    const uint32_t lanoffB =
        (uint32_t)((((lmat >> 1) * 8 + lrow) * KSTRH + (lmat & 1) * 8) * 2);

    // stage Q tile (128x64 halves) into buffer 0, pull A-frags into regs
#pragma unroll
    for (int i = 0; i < 4; i++) {
        int id = i * 256 + t;
        int r = id >> 3, c = (id & 7) << 3;
        cpa16(sb + (r * KSTRH + c) * 2, qb + (size_t)(q0 + r) * EMB + c);
    }
    cpa_commit();
    asm volatile("cp.async.wait_group 0;");
    __syncthreads();
    uint32_t aQ[4][4];
    {
        const uint32_t lanoffA =
            (uint32_t)((((lmat & 1) * 8 + lrow) * KSTRH + (lmat >> 1) * 8) * 2);
#pragma unroll
        for (int kg = 0; kg < 4; kg++)
            ldsm4(aQ[kg][0], aQ[kg][1], aQ[kg][2], aQ[kg][3],
                  sb + (uint32_t)(wm * KSTRH * 2) + lanoffA + kg * 32);
    }
    __syncthreads();

    // prologue: prefetch tile 0 into buffer 0
    {
#pragma unroll
        for (int i = 0; i < 2; i++) {
            int id = i * 256 + t;
            int r = id >> 3, c = (id & 7) << 3;
            cpa16(sb + (r * KSTRH + c) * 2, kb + (size_t)r * EMB + c);
            cpa16(sb + (KELEH + r * KSTRH + c) * 2, vtb + (size_t)r * S_LEN + c);
        }
        cpa_commit();
    }

    float o[8][4] = {};
    float l0 = 0.f, l1 = 0.f;
    int bufc = 0;

    for (int kt = 0; kt < NT; kt++) {
        asm volatile("cp.async.wait_group 0;");  // tile kt landed
        __syncthreads();                         // all warps done with kt-1

        if (kt + 1 < NT) {                       // prefetch kt+1 into buf^1
            const int k0 = (kt + 1) * 64;
            const uint32_t dst = sb + (bufc ^ 1) * (STAGEH * 2);
#pragma unroll
            for (int i = 0; i < 2; i++) {
                int id = i * 256 + t;
                int r = id >> 3, c = (id & 7) << 3;
                cpa16(dst + (r * KSTRH + c) * 2, kb + (size_t)(k0 + r) * EMB + c);
                cpa16(dst + (KELEH + r * KSTRH + c) * 2,
                      vtb + (size_t)r * S_LEN + k0 + c);
            }
            cpa_commit();
        }

        const uint32_t kbase = sb + bufc * (STAGEH * 2) + lanoffB;
        const uint32_t vbase = kbase + KELEH * 2;
        bufc ^= 1;

        // per key-group p: S-slice = Q K^T, exp2, then O += P_slice V_slice.
#pragma unroll
        for (int p = 0; p < 4; p++) {
            float c0[4] = {}, c1[4] = {};
#pragma unroll
            for (int kg = 0; kg < 4; kg++) {
                uint32_t b0, b1, b2, b3;
                ldsm4(b0, b1, b2, b3, kbase + (p * 16 * KSTRH + kg * 16) * 2);
                mma16(c0, aQ[kg], b0, b1);
                mma16(c1, aQ[kg], b2, b3);
            }
            // P = exp2(S) packed; aP is directly the PV A-fragment.
            uint32_t aP[4];
            aP[0] = h2ex2(packh2(c0[0], c0[1]));
            aP[1] = h2ex2(packh2(c0[2], c0[3]));
            aP[2] = h2ex2(packh2(c1[0], c1[1]));
            aP[3] = h2ex2(packh2(c1[2], c1[3]));
            float2 f;
            f = __half22float2(*(__half2*)&aP[0]); l0 += f.x + f.y;
            f = __half22float2(*(__half2*)&aP[2]); l0 += f.x + f.y;
            f = __half22float2(*(__half2*)&aP[1]); l1 += f.x + f.y;
            f = __half22float2(*(__half2*)&aP[3]); l1 += f.x + f.y;
#pragma unroll
            for (int pp = 0; pp < 4; pp++) {
                uint32_t v0, v1, v2, v3;
                ldsm4(v0, v1, v2, v3, vbase + (pp * 16 * KSTRH + p * 16) * 2);
                mma16(o[2 * pp], aP, v0, v1);
                mma16(o[2 * pp + 1], aP, v2, v3);
            }
        }
    }

    // one-shot denominator reduction across the quad
#pragma unroll
    for (int off = 1; off <= 2; off <<= 1) {
        l0 += __shfl_xor_sync(FULLM, l0, off);
        l1 += __shfl_xor_sync(FULLM, l1, off);
    }
    const float inv0 = 1.0f / l0, inv1 = 1.0f / l1;
#pragma unroll
    for (int nb = 0; nb < 8; nb++) {
        size_t base = headOff + (size_t)(q0 + wm + gq) * EMB + nb * 8 + 2 * tq;
        *(uint32_t*)(O + base) = packh2(o[nb][0] * inv0, o[nb][1] * inv0);
        *(uint32_t*)(O + base + (size_t)8 * EMB) =
            packh2(o[nb][2] * inv1, o[nb][3] * inv1);
    }
}

// ---------------------------------------------------------------------------
// Output GEMM: Y(4096x1024) fp32 = X @ Wo^T + bo.  BM=128, BN=128, BK=64.
// 2-stage ring, one barrier per k-tile, ldmatrix.x4.  grid=256, 8 warps.
// ---------------------------------------------------------------------------
#define OSTRH 72
#define XELEH (128 * OSTRH)
#define OSTAGEH (2 * XELEH)
#define NKT (EMB / 64)

extern __shared__ __half og_smem[];

__global__ __launch_bounds__(256) void out_tc(const __half* __restrict__ X,
                                              const __half* __restrict__ W,
                                              const float* __restrict__ bias,
                                              float* __restrict__ Y) {
    __half* smem = og_smem;
    const int t = threadIdx.x, lane = t & 31, warp = t >> 5;
    const int tq = lane & 3, gq = lane >> 2;
    const int wm = warp * 16;
    const int lrow = lane & 7, lmat = lane >> 3;
    const int m0 = blockIdx.x * 128, n0 = blockIdx.y * 128;
    const uint32_t sb = (uint32_t)__cvta_generic_to_shared(smem);
    const uint32_t lanoffA =
        (uint32_t)((((lmat & 1) * 8 + lrow) * OSTRH + (lmat >> 1) * 8) * 2);
    const uint32_t lanoffB =
        (uint32_t)((((lmat >> 1) * 8 + lrow) * OSTRH + (lmat & 1) * 8) * 2);

    // prologue: prefetch k-tile 0 into buffer 0
    {
#pragma unroll
        for (int i = 0; i < 4; i++) {
            int id = i * 256 + t;
            int r = id >> 3, c = (id & 7) << 3;
            cpa16(sb + (r * OSTRH + c) * 2, X + (size_t)(m0 + r) * EMB + c);
            cpa16(sb + (XELEH + r * OSTRH + c) * 2, W + (size_t)(n0 + r) * EMB + c);
        }
        cpa_commit();
    }

    float acc[16][4] = {};
    int bufc = 0;
    for (int kt = 0; kt < NKT; kt++) {
        asm volatile("cp.async.wait_group 0;");
        __syncthreads();

        if (kt + 1 < NKT) {
            const int k0 = (kt + 1) * 64;
            const uint32_t dst = sb + (bufc ^ 1) * (OSTAGEH * 2);
#pragma unroll
            for (int i = 0; i < 4; i++) {
                int id = i * 256 + t;
                int r = id >> 3, c = (id & 7) << 3;
                cpa16(dst + (r * OSTRH + c) * 2, X + (size_t)(m0 + r) * EMB + k0 + c);
                cpa16(dst + (XELEH + r * OSTRH + c) * 2,
                      W + (size_t)(n0 + r) * EMB + k0 + c);
            }
            cpa_commit();
        }

        const uint32_t xbase = sb + bufc * (OSTAGEH * 2) +
                               (uint32_t)(wm * OSTRH * 2) + lanoffA;
        const uint32_t wbase = sb + bufc * (OSTAGEH * 2) + XELEH * 2 + lanoffB;
        bufc ^= 1;
#pragma unroll
        for (int kg = 0; kg < 4; kg++) {
            uint32_t a[4];
            ldsm4(a[0], a[1], a[2], a[3], xbase + kg * 32);
#pragma unroll
            for (int p = 0; p < 8; p++) {
                uint32_t r0, r1, r2, r3;
                ldsm4(r0, r1, r2, r3, wbase + (p * 16 * OSTRH + kg * 16) * 2);
                mma16(acc[2 * p], a, r0, r1);
                mma16(acc[2 * p + 1], a, r2, r3);
            }
        }
    }

#pragma unroll
    for (int nb = 0; nb < 16; nb++) {
        int col = n0 + nb * 8 + 2 * tq;
        float b0 = __ldg(bias + col), b1 = __ldg(bias + col + 1);
        size_t base = (size_t)(m0 + wm + gq) * EMB + col;
        *(float2*)(Y + base) = make_float2(acc[nb][0] + b0, acc[nb][1] + b1);
        *(float2*)(Y + base + (size_t)8 * EMB) =
            make_float2(acc[nb][2] + b0, acc[nb][3] + b1);
    }
}

// ---------------------------------------------------------------------------
extern "C" void kernel_launch(void* const* d_in, const int* in_sizes, int n_in,
                              void* d_out, int out_size) {
    const float* q  = (const float*)d_in[0];
    const float* k  = (const float*)d_in[1];
    const float* v  = (const float*)d_in[2];
    const float* Wq = (const float*)d_in[3];
    const float* Wk = (const float*)d_in[4];
    const float* Wv = (const float*)d_in[5];
    const float* Wo = (const float*)d_in[6];
    const float* bo = (const float*)d_in[7];
    float* out = (float*)d_out;

    __half *qp, *kp, *vp, *vt, *ao, *wo;
    cudaGetSymbolAddress((void**)&qp, g_qp);
    cudaGetSymbolAddress((void**)&kp, g_kp);
    cudaGetSymbolAddress((void**)&vp, g_vp);
    cudaGetSymbolAddress((void**)&vt, g_vt);
    cudaGetSymbolAddress((void**)&ao, g_ao);
    cudaGetSymbolAddress((void**)&wo, g_wo);

    static bool attr_done = false;
    if (!attr_done) {
        cudaFuncSetAttribute(flash_tc, cudaFuncAttributeMaxDynamicSharedMemorySize,
                             2 * STAGEH * 2);
        cudaFuncSetAttribute(out_tc, cudaFuncAttributeMaxDynamicSharedMemorySize,
                             2 * OSTAGEH * 2);
        attr_done = true;
    }

    cvt_wo<<<1024, 256>>>(Wo, wo);
    proj_tc<<<dim3(1024, 3), 128>>>(q, k, v, Wq, Wk, Wv, qp, kp, vp);
    transp_v<<<dim3(S_LEN / 64, N_B * HEADS), 256>>>(vp, vt);
    flash_tc<<<dim3(S_LEN / 128, N_B * HEADS), 256, 2 * STAGEH * 2>>>(qp, kp, vt, ao);
    out_tc<<<dim3((N_B * S_LEN) / 128, EMB / 128), 256, 2 * OSTAGEH * 2>>>(ao, wo, bo, out);
}

// round 14
// speedup vs baseline: 1.1874x; 1.0495x over previous
#include <cuda_runtime.h>
#include <cuda_fp16.h>
#include <cstdint>
#include <cstddef>

#define N_B   2
#define S_LEN 2048
#define HEADS 16
#define HDIM  64
#define EMB   1024
// 1/sqrt(1024) * log2(e): softmax runs in exp2 domain
#define QSCALE (0.03125f * 1.44269504088896340736f)
#define FULLM 0xffffffffu

// Scratch (alloc-free rule: __device__ globals), fp16.
__device__ __half g_qp[N_B * S_LEN * EMB];
__device__ __half g_kp[N_B * S_LEN * EMB];
__device__ __half g_vp[N_B * S_LEN * EMB];   // (n,s,h,d) projected V
__device__ __half g_vt[N_B * HEADS * HDIM * S_LEN]; // (n,h,d,s) transposed V
__device__ __half g_ao[N_B * S_LEN * EMB];
__device__ __half g_wo[EMB * EMB];

__device__ __forceinline__ uint32_t packh2(float lo, float hi) {
    __half2 h = __floats2half2_rn(lo, hi);
    return *(uint32_t*)&h;
}
// exp2 on a packed half2 (one MUFU op for two values)
__device__ __forceinline__ uint32_t h2ex2(uint32_t x) {
    uint32_t r;
    asm("ex2.approx.f16x2 %0, %1;" : "=r"(r) : "r"(x));
    return r;
}
#define LDU32(p) (*(const uint32_t*)(p))

// D(16x8) += A(16x16)*B(16x8), fp16 in, fp32 accum.
__device__ __forceinline__ void mma16(float* c, const uint32_t* a,
                                      uint32_t b0, uint32_t b1) {
    asm volatile(
        "mma.sync.aligned.m16n8k16.row.col.f32.f16.f16.f32 "
        "{%0,%1,%2,%3},{%4,%5,%6,%7},{%8,%9},{%0,%1,%2,%3};"
        : "+f"(c[0]), "+f"(c[1]), "+f"(c[2]), "+f"(c[3])
        : "r"(a[0]), "r"(a[1]), "r"(a[2]), "r"(a[3]), "r"(b0), "r"(b1));
}

// 4x 8x8 b16 fragments in one shot, mma-ready layout
__device__ __forceinline__ void ldsm4(uint32_t& r0, uint32_t& r1,
                                      uint32_t& r2, uint32_t& r3, uint32_t a) {
    asm volatile("ldmatrix.sync.aligned.m8n8.x4.shared.b16 {%0,%1,%2,%3}, [%4];"
                 : "=r"(r0), "=r"(r1), "=r"(r2), "=r"(r3) : "r"(a));
}

__device__ __forceinline__ void cpa16(uint32_t s, const void* g) {
    asm volatile("cp.async.ca.shared.global [%0], [%1], 16;" :: "r"(s), "l"(g));
}
__device__ __forceinline__ void cpa_commit() {
    asm volatile("cp.async.commit_group;");
}

// ---------------------------------------------------------------------------
// Wo fp32 -> fp16
// ---------------------------------------------------------------------------
__global__ __launch_bounds__(256) void cvt_wo(const float* __restrict__ W,
                                              __half* __restrict__ Y) {
    int i = (blockIdx.x * 256 + threadIdx.x) * 4;
    float4 v = *(const float4*)(W + i);
    uint2 o = make_uint2(packh2(v.x, v.y), packh2(v.z, v.w));
    *(uint2*)(Y + i) = o;
}

// ---------------------------------------------------------------------------
// Projection: Y(65536x64) fp16 = rn_h((X @ W^T) * sc).  Q gets QSCALE.
// ---------------------------------------------------------------------------
#define PSTR 72
__global__ __launch_bounds__(128) void proj_tc(const float* __restrict__ xq,
                                               const float* __restrict__ xk,
                                               const float* __restrict__ xv,
                                               const float* __restrict__ wq,
                                               const float* __restrict__ wk,
                                               const float* __restrict__ wv,
                                               __half* __restrict__ yq,
                                               __half* __restrict__ yk,
                                               __half* __restrict__ yv) {
    __shared__ __half Xs[64 * PSTR];
    __shared__ __half Ws[64 * PSTR];
    const int t = threadIdx.x, lane = t & 31, warp = t >> 5;
    const int tq = lane & 3, gq = lane >> 2;
    const int wm = warp * 16;
    const int rowBase = blockIdx.x * 64;
    const int which = blockIdx.y;
    const float* X = (which == 0) ? xq : (which == 1) ? xk : xv;
    const float* W = (which == 0) ? wq : (which == 1) ? wk : wv;
    __half* Y = (which == 0) ? yq : (which == 1) ? yk : yv;
    const float sc = (which == 0) ? QSCALE : 1.0f;

#pragma unroll
    for (int i = 0; i < 8; i++) {
        int idx = i * 128 + t;
        int r = idx >> 4, c = (idx & 15) << 2;
        float4 v = *(const float4*)(X + (size_t)(rowBase + r) * 64 + c);
        *(uint2*)(&Xs[r * PSTR + c]) = make_uint2(packh2(v.x, v.y), packh2(v.z, v.w));
        float4 w = *(const float4*)(W + r * 64 + c);
        *(uint2*)(&Ws[r * PSTR + c]) = make_uint2(packh2(w.x, w.y), packh2(w.z, w.w));
    }
    __syncthreads();

    float c[8][4] = {};
#pragma unroll
    for (int kg = 0; kg < 4; kg++) {
        const int kk = kg * 16 + 2 * tq;
        uint32_t a[4] = { LDU32(&Xs[(wm + gq) * PSTR + kk]),
                          LDU32(&Xs[(wm + gq + 8) * PSTR + kk]),
                          LDU32(&Xs[(wm + gq) * PSTR + kk + 8]),
                          LDU32(&Xs[(wm + gq + 8) * PSTR + kk + 8]) };
        uint32_t b0[8], b1[8];
#pragma unroll
        for (int nb = 0; nb < 8; nb++) {
            b0[nb] = LDU32(&Ws[(nb * 8 + gq) * PSTR + kk]);
            b1[nb] = LDU32(&Ws[(nb * 8 + gq) * PSTR + kk + 8]);
        }
#pragma unroll
        for (int nb = 0; nb < 8; nb++) mma16(c[nb], a, b0[nb], b1[nb]);
    }
#pragma unroll
    for (int nb = 0; nb < 8; nb++) {
        size_t base = (size_t)(rowBase + wm + gq) * 64 + nb * 8 + 2 * tq;
        *(uint32_t*)(Y + base) = packh2(c[nb][0] * sc, c[nb][1] * sc);
        *(uint32_t*)(Y + base + 8 * 64) = packh2(c[nb][2] * sc, c[nb][3] * sc);
    }
}

// ---------------------------------------------------------------------------
// V transpose: vp (n,s,h,d) -> vt (n,h,d,s).
// ---------------------------------------------------------------------------
__global__ __launch_bounds__(256) void transp_v(const __half* __restrict__ vp,
                                                __half* __restrict__ vt) {
    __shared__ __half Ts[64][66];
    const int t = threadIdx.x;
    const int s0 = blockIdx.x * 64;
    const int nh = blockIdx.y;
    const int n = nh >> 4, h = nh & 15;
    const __half* src = vp + ((size_t)n * S_LEN * HEADS + h) * HDIM;
#pragma unroll
    for (int i = 0; i < 8; i++) {
        int id = i * 256 + t;
        int r = id >> 5;
        int c = (id & 31) * 2;
        __half2 v = *(const __half2*)(src + (size_t)(s0 + r) * EMB + c);
        Ts[c][r] = v.x;
        Ts[c + 1][r] = v.y;
    }
    __syncthreads();
    __half* dst = vt + (size_t)nh * HDIM * S_LEN;
#pragma unroll
    for (int i = 0; i < 8; i++) {
        int id = i * 256 + t;
        int d = id >> 5;
        int s = (id & 31) * 2;
        __half2 v;
        v.x = Ts[d][s];
        v.y = Ts[d][s + 1];
        *(__half2*)(dst + (size_t)d * S_LEN + s0 + s) = v;
    }
}

// ---------------------------------------------------------------------------
// Flash attention fp16, M=32 per warp (two 16-row strips): halves LDSM per
// MMA (0.25) so the tensor pipe, not the smem crossbar, is the bound.
// BM=128, 4 warps, 128 threads.  Fixed-max exp2 softmax (f16x2 MUFU),
// ldmatrix.x4, 2-stage ring w/ one barrier per tile.
// grid=(S/128, N*H).
// ---------------------------------------------------------------------------
#define KSTRH 72
#define KELEH (64 * KSTRH)
#define STAGEH (2 * KELEH)      // K tile + V tile (halves)
#define NT (S_LEN / 64)

extern __shared__ __half fa_smem[];

__global__ __launch_bounds__(128, 3) void flash_tc(const __half* __restrict__ Q,
                                                   const __half* __restrict__ K,
                                                   const __half* __restrict__ Vt,
                                                   __half* __restrict__ O) {
    __half* smem = fa_smem;
    const int t = threadIdx.x, lane = t & 31, warp = t >> 5;
    const int tq = lane & 3, gq = lane >> 2;
    const int wm = warp * 32;           // 32 query rows per warp
    const int lrow = lane & 7, lmat = lane >> 3;
    const int qt = blockIdx.x, nh = blockIdx.y;
    const int n = nh >> 4, h = nh & 15;
    const size_t headOff = ((size_t)n * S_LEN * HEADS + h) * HDIM;
    const __half* qb = Q + headOff;
    const __half* kb = K + headOff;
    const __half* vtb = Vt + (size_t)nh * HDIM * S_LEN;
    const int q0 = qt * 128;
    const uint32_t sb = (uint32_t)__cvta_generic_to_shared(smem);
    const uint32_t lanoffB =
        (uint32_t)((((lmat >> 1) * 8 + lrow) * KSTRH + (lmat & 1) * 8) * 2);

    // stage Q tile (128x64 halves) into buffer 0, pull A-frags (2 strips)
#pragma unroll
    for (int i = 0; i < 8; i++) {
        int id = i * 128 + t;
        int r = id >> 3, c = (id & 7) << 3;
        cpa16(sb + (r * KSTRH + c) * 2, qb + (size_t)(q0 + r) * EMB + c);
    }
    cpa_commit();
    asm volatile("cp.async.wait_group 0;");
    __syncthreads();
    uint32_t aQ[4][8];   // [kg][strip0:0..3, strip1:4..7]
    {
        const uint32_t lanoffA =
            (uint32_t)((((lmat & 1) * 8 + lrow) * KSTRH + (lmat >> 1) * 8) * 2);
#pragma unroll
        for (int kg = 0; kg < 4; kg++) {
            ldsm4(aQ[kg][0], aQ[kg][1], aQ[kg][2], aQ[kg][3],
                  sb + (uint32_t)(wm * KSTRH * 2) + lanoffA + kg * 32);
            ldsm4(aQ[kg][4], aQ[kg][5], aQ[kg][6], aQ[kg][7],
                  sb + (uint32_t)((wm + 16) * KSTRH * 2) + lanoffA + kg * 32);
        }
    }
    __syncthreads();

    // prologue: prefetch tile 0 into buffer 0
    {
#pragma unroll
        for (int i = 0; i < 4; i++) {
            int id = i * 128 + t;
            int r = id >> 3, c = (id & 7) << 3;
            cpa16(sb + (r * KSTRH + c) * 2, kb + (size_t)r * EMB + c);
            cpa16(sb + (KELEH + r * KSTRH + c) * 2, vtb + (size_t)r * S_LEN + c);
        }
        cpa_commit();
    }

    float o[16][4] = {};   // [0..7]: strip0 dims, [8..15]: strip1 dims
    float l0 = 0.f, l1 = 0.f, l2 = 0.f, l3 = 0.f;
    int bufc = 0;

    for (int kt = 0; kt < NT; kt++) {
        asm volatile("cp.async.wait_group 0;");  // tile kt landed
        __syncthreads();                         // all warps done with kt-1

        if (kt + 1 < NT) {                       // prefetch kt+1 into buf^1
            const int k0 = (kt + 1) * 64;
            const uint32_t dst = sb + (bufc ^ 1) * (STAGEH * 2);
#pragma unroll
            for (int i = 0; i < 4; i++) {
                int id = i * 128 + t;
                int r = id >> 3, c = (id & 7) << 3;
                cpa16(dst + (r * KSTRH + c) * 2, kb + (size_t)(k0 + r) * EMB + c);
                cpa16(dst + (KELEH + r * KSTRH + c) * 2,
                      vtb + (size_t)r * S_LEN + k0 + c);
            }
            cpa_commit();
        }

        const uint32_t kbase = sb + bufc * (STAGEH * 2) + lanoffB;
        const uint32_t vbase = kbase + KELEH * 2;
        bufc ^= 1;

        // per key-group p: S-slices for both strips, exp2, then PV for both
        // strips reusing ONE set of V fragment loads.
#pragma unroll
        for (int p = 0; p < 4; p++) {
            float c0[4] = {}, c1[4] = {}, c2[4] = {}, c3[4] = {};
#pragma unroll
            for (int kg = 0; kg < 4; kg++) {
                uint32_t b0, b1, b2, b3;
                ldsm4(b0, b1, b2, b3, kbase + (p * 16 * KSTRH + kg * 16) * 2);
                mma16(c0, aQ[kg], b0, b1);
                mma16(c1, aQ[kg], b2, b3);
                mma16(c2, aQ[kg] + 4, b0, b1);
                mma16(c3, aQ[kg] + 4, b2, b3);
            }
            uint32_t aP0[4], aP1[4];
            aP0[0] = h2ex2(packh2(c0[0], c0[1]));
            aP0[1] = h2ex2(packh2(c0[2], c0[3]));
            aP0[2] = h2ex2(packh2(c1[0], c1[1]));
            aP0[3] = h2ex2(packh2(c1[2], c1[3]));
            aP1[0] = h2ex2(packh2(c2[0], c2[1]));
            aP1[1] = h2ex2(packh2(c2[2], c2[3]));
            aP1[2] = h2ex2(packh2(c3[0], c3[1]));
            aP1[3] = h2ex2(packh2(c3[2], c3[3]));
            float2 f;
            f = __half22float2(*(__half2*)&aP0[0]); l0 += f.x + f.y;
            f = __half22float2(*(__half2*)&aP0[2]); l0 += f.x + f.y;
            f = __half22float2(*(__half2*)&aP0[1]); l1 += f.x + f.y;
            f = __half22float2(*(__half2*)&aP0[3]); l1 += f.x + f.y;
            f = __half22float2(*(__half2*)&aP1[0]); l2 += f.x + f.y;
            f = __half22float2(*(__half2*)&aP1[2]); l2 += f.x + f.y;
            f = __half22float2(*(__half2*)&aP1[1]); l3 += f.x + f.y;
            f = __half22float2(*(__half2*)&aP1[3]); l3 += f.x + f.y;
#pragma unroll
            for (int pp = 0; pp < 4; pp++) {
                uint32_t v0, v1, v2, v3;
                ldsm4(v0, v1, v2, v3, vbase + (pp * 16 * KSTRH + p * 16) * 2);
                mma16(o[2 * pp], aP0, v0, v1);
                mma16(o[2 * pp + 1], aP0, v2, v3);
                mma16(o[8 + 2 * pp], aP1, v0, v1);
                mma16(o[8 + 2 * pp + 1], aP1, v2, v3);
            }
        }
    }

    // one-shot denominator reduction across the quad
#pragma unroll
    for (int off = 1; off <= 2; off <<= 1) {
        l0 += __shfl_xor_sync(FULLM, l0, off);
        l1 += __shfl_xor_sync(FULLM, l1, off);
        l2 += __shfl_xor_sync(FULLM, l2, off);
        l3 += __shfl_xor_sync(FULLM, l3, off);
    }
    const float i0 = 1.0f / l0, i1 = 1.0f / l1;
    const float i2 = 1.0f / l2, i3 = 1.0f / l3;
#pragma unroll
    for (int nb = 0; nb < 8; nb++) {
        size_t base = headOff + (size_t)(q0 + wm + gq) * EMB + nb * 8 + 2 * tq;
        *(uint32_t*)(O + base) = packh2(o[nb][0] * i0, o[nb][1] * i0);
        *(uint32_t*)(O + base + (size_t)8 * EMB) =
            packh2(o[nb][2] * i1, o[nb][3] * i1);
        size_t base2 = base + (size_t)16 * EMB;
        *(uint32_t*)(O + base2) = packh2(o[8 + nb][0] * i2, o[8 + nb][1] * i2);
        *(uint32_t*)(O + base2 + (size_t)8 * EMB) =
            packh2(o[8 + nb][2] * i3, o[8 + nb][3] * i3);
    }
}

// ---------------------------------------------------------------------------
// Output GEMM: Y(4096x1024) fp32 = X @ Wo^T + bo.  BM=128, BN=128, BK=64.
// 2-stage ring, one barrier per k-tile, ldmatrix.x4.  grid=256, 8 warps.
// ---------------------------------------------------------------------------
#define OSTRH 72
#define XELEH (128 * OSTRH)
#define OSTAGEH (2 * XELEH)
#define NKT (EMB / 64)

extern __shared__ __half og_smem[];

__global__ __launch_bounds__(256) void out_tc(const __half* __restrict__ X,
                                              const __half* __restrict__ W,
                                              const float* __restrict__ bias,
                                              float* __restrict__ Y) {
    __half* smem = og_smem;
    const int t = threadIdx.x, lane = t & 31, warp = t >> 5;
    const int tq = lane & 3, gq = lane >> 2;
    const int wm = warp * 16;
    const int lrow = lane & 7, lmat = lane >> 3;
    const int m0 = blockIdx.x * 128, n0 = blockIdx.y * 128;
    const uint32_t sb = (uint32_t)__cvta_generic_to_shared(smem);
    const uint32_t lanoffA =
        (uint32_t)((((lmat & 1) * 8 + lrow) * OSTRH + (lmat >> 1) * 8) * 2);
    const uint32_t lanoffB =
        (uint32_t)((((lmat >> 1) * 8 + lrow) * OSTRH + (lmat & 1) * 8) * 2);

    // prologue: prefetch k-tile 0 into buffer 0
    {
#pragma unroll
        for (int i = 0; i < 4; i++) {
            int id = i * 256 + t;
            int r = id >> 3, c = (id & 7) << 3;
            cpa16(sb + (r * OSTRH + c) * 2, X + (size_t)(m0 + r) * EMB + c);
            cpa16(sb + (XELEH + r * OSTRH + c) * 2, W + (size_t)(n0 + r) * EMB + c);
        }
        cpa_commit();
    }

    float acc[16][4] = {};
    int bufc = 0;
    for (int kt = 0; kt < NKT; kt++) {
        asm volatile("cp.async.wait_group 0;");
        __syncthreads();

        if (kt + 1 < NKT) {
            const int k0 = (kt + 1) * 64;
            const uint32_t dst = sb + (bufc ^ 1) * (OSTAGEH * 2);
#pragma unroll
            for (int i = 0; i < 4; i++) {
                int id = i * 256 + t;
                int r = id >> 3, c = (id & 7) << 3;
                cpa16(dst + (r * OSTRH + c) * 2, X + (size_t)(m0 + r) * EMB + k0 + c);
                cpa16(dst + (XELEH + r * OSTRH + c) * 2,
                      W + (size_t)(n0 + r) * EMB + k0 + c);
            }
            cpa_commit();
        }

        const uint32_t xbase = sb + bufc * (OSTAGEH * 2) +
                               (uint32_t)(wm * OSTRH * 2) + lanoffA;
        const uint32_t wbase = sb + bufc * (OSTAGEH * 2) + XELEH * 2 + lanoffB;
        bufc ^= 1;
#pragma unroll
        for (int kg = 0; kg < 4; kg++) {
            uint32_t a[4];
            ldsm4(a[0], a[1], a[2], a[3], xbase + kg * 32);
#pragma unroll
            for (int p = 0; p < 8; p++) {
                uint32_t r0, r1, r2, r3;
                ldsm4(r0, r1, r2, r3, wbase + (p * 16 * OSTRH + kg * 16) * 2);
                mma16(acc[2 * p], a, r0, r1);
                mma16(acc[2 * p + 1], a, r2, r3);
            }
        }
    }

#pragma unroll
    for (int nb = 0; nb < 16; nb++) {
        int col = n0 + nb * 8 + 2 * tq;
        float b0 = __ldg(bias + col), b1 = __ldg(bias + col + 1);
        size_t base = (size_t)(m0 + wm + gq) * EMB + col;
        *(float2*)(Y + base) = make_float2(acc[nb][0] + b0, acc[nb][1] + b1);
        *(float2*)(Y + base + (size_t)8 * EMB) =
            make_float2(acc[nb][2] + b0, acc[nb][3] + b1);
    }
}

// ---------------------------------------------------------------------------
extern "C" void kernel_launch(void* const* d_in, const int* in_sizes, int n_in,
                              void* d_out, int out_size) {
    const float* q  = (const float*)d_in[0];
    const float* k  = (const float*)d_in[1];
    const float* v  = (const float*)d_in[2];
    const float* Wq = (const float*)d_in[3];
    const float* Wk = (const float*)d_in[4];
    const float* Wv = (const float*)d_in[5];
    const float* Wo = (const float*)d_in[6];
    const float* bo = (const float*)d_in[7];
    float* out = (float*)d_out;

    __half *qp, *kp, *vp, *vt, *ao, *wo;
    cudaGetSymbolAddress((void**)&qp, g_qp);
    cudaGetSymbolAddress((void**)&kp, g_kp);
    cudaGetSymbolAddress((void**)&vp, g_vp);
    cudaGetSymbolAddress((void**)&vt, g_vt);
    cudaGetSymbolAddress((void**)&ao, g_ao);
    cudaGetSymbolAddress((void**)&wo, g_wo);

    static bool attr_done = false;
    if (!attr_done) {
        cudaFuncSetAttribute(flash_tc, cudaFuncAttributeMaxDynamicSharedMemorySize,
                             2 * STAGEH * 2);
        cudaFuncSetAttribute(out_tc, cudaFuncAttributeMaxDynamicSharedMemorySize,
                             2 * OSTAGEH * 2);
        attr_done = true;
    }

    cvt_wo<<<1024, 256>>>(Wo, wo);
    proj_tc<<<dim3(1024, 3), 128>>>(q, k, v, Wq, Wk, Wv, qp, kp, vp);
    transp_v<<<dim3(S_LEN / 64, N_B * HEADS), 256>>>(vp, vt);
    flash_tc<<<dim3(S_LEN / 128, N_B * HEADS), 128, 2 * STAGEH * 2>>>(qp, kp, vt, ao);
    out_tc<<<dim3((N_B * S_LEN) / 128, EMB / 128), 256, 2 * OSTAGEH * 2>>>(ao, wo, bo, out);
}